// round 1
// baseline (speedup 1.0000x reference)
#include <cuda_runtime.h>
#include <cuda_bf16.h>
#include <math.h>

// Problem constants
#define BB 4
#define TT 1024
#define EE 1024
#define HH 16
#define DD 64
#define FF 4096
#define LL 6
#define VV 32000
#define MM (BB*TT)          // 4096 rows in the token dimension
#define LN_EPS 1e-5f

// ---------------------------------------------------------------------------
// Scratch (device globals; no cudaMalloc allowed)
// ---------------------------------------------------------------------------
__device__ float g_x[(size_t)MM * EE];            // residual stream (16MB)
__device__ float g_h[(size_t)MM * EE];            // LN output
__device__ float g_q[(size_t)MM * EE];
__device__ float g_k[(size_t)MM * EE];
__device__ float g_v[(size_t)MM * EE];
__device__ float g_o[(size_t)MM * EE];            // attention output
__device__ float g_f[(size_t)MM * FF];            // FFN mid (64MB)
__device__ float g_s[(size_t)BB * HH * TT * TT];  // attention scores (256MB)

// ---------------------------------------------------------------------------
// Embedding: x[bt,e] = wte[idx[bt],e] + wpe[bt%T,e]
// ---------------------------------------------------------------------------
__global__ void embed_kernel(const int* __restrict__ idx,
                             const float* __restrict__ wte,
                             const float* __restrict__ wpe,
                             float* __restrict__ x)
{
    long long i = (long long)blockIdx.x * blockDim.x + threadIdx.x; // < MM*EE
    int bt = (int)(i >> 10);      // E = 1024
    int e  = (int)(i & 1023);
    int t  = bt & (TT - 1);
    x[i] = wte[(long long)idx[bt] * EE + e] + wpe[(long long)t * EE + e];
}

// ---------------------------------------------------------------------------
// LayerNorm: one block (256 threads) per row of 1024
// ---------------------------------------------------------------------------
__device__ __forceinline__ float warp_sum(float v) {
    #pragma unroll
    for (int o = 16; o > 0; o >>= 1) v += __shfl_xor_sync(0xffffffffu, v, o);
    return v;
}

__global__ __launch_bounds__(256) void ln_kernel(const float* __restrict__ x,
                                                 const float* __restrict__ gamma,
                                                 const float* __restrict__ beta,
                                                 float* __restrict__ out)
{
    int row = blockIdx.x;
    const float* xr = x + (long long)row * EE;
    float* orow = out + (long long)row * EE;
    int tid = threadIdx.x;

    float s = 0.f, s2 = 0.f;
    float vals[4];
    #pragma unroll
    for (int u = 0; u < 4; u++) {
        float v = xr[tid + u * 256];
        vals[u] = v;
        s += v; s2 += v * v;
    }
    s  = warp_sum(s);
    s2 = warp_sum(s2);
    __shared__ float shs[8], shs2[8];
    int wid = tid >> 5, lane = tid & 31;
    if (lane == 0) { shs[wid] = s; shs2[wid] = s2; }
    __syncthreads();
    float ts = 0.f, ts2 = 0.f;
    #pragma unroll
    for (int i = 0; i < 8; i++) { ts += shs[i]; ts2 += shs2[i]; }
    float mean = ts * (1.0f / EE);
    float var  = ts2 * (1.0f / EE) - mean * mean;
    float rstd = rsqrtf(var + LN_EPS);
    #pragma unroll
    for (int u = 0; u < 4; u++) {
        int j = tid + u * 256;
        orow[j] = (vals[u] - mean) * rstd * gamma[j] + beta[j];
    }
}

// ---------------------------------------------------------------------------
// Causal softmax over score rows. grid = (T, B*H); block = 256.
// Writes normalized probs for j<=t, zeros for j>t.
// ---------------------------------------------------------------------------
__global__ __launch_bounds__(256) void softmax_kernel(float* __restrict__ S)
{
    int t  = blockIdx.x;
    int bh = blockIdx.y;
    float* row = S + ((long long)bh * TT + t) * (long long)TT;
    int tid = threadIdx.x;

    __shared__ float sh[8];
    int wid = tid >> 5, lane = tid & 31;

    // max over valid region
    float mx = -INFINITY;
    for (int j = tid; j <= t; j += 256) mx = fmaxf(mx, row[j]);
    #pragma unroll
    for (int o = 16; o > 0; o >>= 1) mx = fmaxf(mx, __shfl_xor_sync(0xffffffffu, mx, o));
    if (lane == 0) sh[wid] = mx;
    __syncthreads();
    float m = sh[0];
    #pragma unroll
    for (int i = 1; i < 8; i++) m = fmaxf(m, sh[i]);
    __syncthreads();

    // exp + sum; write exp for valid, 0 for masked
    float sum = 0.f;
    for (int j = tid; j < TT; j += 256) {
        float e = (j <= t) ? __expf(row[j] - m) : 0.f;
        row[j] = e;
        sum += e;
    }
    sum = warp_sum(sum);
    if (lane == 0) sh[wid] = sum;
    __syncthreads();
    float tot = 0.f;
    #pragma unroll
    for (int i = 0; i < 8; i++) tot += sh[i];
    float inv = 1.0f / tot;
    for (int j = tid; j <= t; j += 256) row[j] *= inv;
}

// ---------------------------------------------------------------------------
// Generic tiled fp32 GEMM. C[M,N] = epi( alpha * A[M,K] @ B(opt transposed) )
//   TB=false: B is K x N (ldb over N)
//   TB=true : B is N x K (ldb over K)  -> C = A @ B^T
// Batched: z in [0,batch), sub-batch decode z -> (z/nh, z%nh) with separate
// outer/inner strides per operand.
// epi: 0 = store; 1 = gelu(acc+bias); 2 = C += acc + bias; 3 = C += acc
// causal!=0: skip blocks entirely above the diagonal (n0 > m0+BM-1)
// ---------------------------------------------------------------------------
#define GBM 64
#define GBN 64
#define GBK 16

template<bool TB>
__global__ __launch_bounds__(256) void gemm_kernel(
    const float* __restrict__ A, const float* __restrict__ Bm,
    const float* __restrict__ bias, float* __restrict__ C,
    int M, int N, int K, int lda, int ldb, int ldc,
    int nh,
    long long sAo, long long sAi, long long sBo, long long sBi,
    long long sCo, long long sCi,
    int epi, float alpha, int causal)
{
    int z = blockIdx.z;
    A  += (long long)(z / nh) * sAo + (long long)(z % nh) * sAi;
    Bm += (long long)(z / nh) * sBo + (long long)(z % nh) * sBi;
    C  += (long long)(z / nh) * sCo + (long long)(z % nh) * sCi;

    int n0 = blockIdx.x * GBN;
    int m0 = blockIdx.y * GBM;
    if (causal && n0 > m0 + GBM - 1) return;

    __shared__ float As[GBK][GBM];
    __shared__ float Bs[GBK][GBN];

    int tid = threadIdx.x;
    int tx = tid & 15;       // col group
    int ty = tid >> 4;       // row group

    float acc[4][4] = {};

    for (int k0 = 0; k0 < K; k0 += GBK) {
        // A tile: A[m0+r][k0+c..c+3] -> As[c..][r] (k-major)
        {
            int r = tid >> 2;
            int c = (tid & 3) << 2;
            float4 a = *(const float4*)(A + (long long)(m0 + r) * lda + k0 + c);
            As[c + 0][r] = a.x; As[c + 1][r] = a.y;
            As[c + 2][r] = a.z; As[c + 3][r] = a.w;
        }
        if (!TB) {
            int r = tid >> 4;          // k
            int c = (tid & 15) << 2;   // n
            float4 b = *(const float4*)(Bm + (long long)(k0 + r) * ldb + n0 + c);
            *(float4*)&Bs[r][c] = b;
        } else {
            int r = tid >> 2;          // n
            int c = (tid & 3) << 2;    // k
            float4 b = *(const float4*)(Bm + (long long)(n0 + r) * ldb + k0 + c);
            Bs[c + 0][r] = b.x; Bs[c + 1][r] = b.y;
            Bs[c + 2][r] = b.z; Bs[c + 3][r] = b.w;
        }
        __syncthreads();

        #pragma unroll
        for (int kk = 0; kk < GBK; kk++) {
            float a[4], b[4];
            *(float4*)a = *(const float4*)&As[kk][ty << 2];
            *(float4*)b = *(const float4*)&Bs[kk][tx << 2];
            #pragma unroll
            for (int i = 0; i < 4; i++)
                #pragma unroll
                for (int j = 0; j < 4; j++)
                    acc[i][j] += a[i] * b[j];
        }
        __syncthreads();
    }

    #pragma unroll
    for (int i = 0; i < 4; i++) {
        int m = m0 + (ty << 2) + i;
        #pragma unroll
        for (int j = 0; j < 4; j++) {
            int n = n0 + (tx << 2) + j;
            float v = acc[i][j] * alpha;
            long long ci = (long long)m * ldc + n;
            if (epi == 1) {
                v += bias[n];
                v = 0.5f * v * (1.0f + erff(v * 0.70710678118654752f));
            } else if (epi == 2) {
                v += bias[n] + C[ci];
            } else if (epi == 3) {
                v += C[ci];
            }
            C[ci] = v;
        }
    }
}

// ---------------------------------------------------------------------------
// Host-side launch helpers
// ---------------------------------------------------------------------------
static inline void gemm(const float* A, const float* B, const float* bias, float* C,
                        int M, int N, int K, int lda, int ldb, int ldc, bool tb,
                        int batch, int nh,
                        long long sAo, long long sAi, long long sBo, long long sBi,
                        long long sCo, long long sCi,
                        int epi, float alpha, int causal)
{
    dim3 grid(N / GBN, M / GBM, batch), block(256);
    if (tb)
        gemm_kernel<true><<<grid, block>>>(A, B, bias, C, M, N, K, lda, ldb, ldc,
                                           nh, sAo, sAi, sBo, sBi, sCo, sCi,
                                           epi, alpha, causal);
    else
        gemm_kernel<false><<<grid, block>>>(A, B, bias, C, M, N, K, lda, ldb, ldc,
                                            nh, sAo, sAi, sBo, sBi, sCo, sCi,
                                            epi, alpha, causal);
}

extern "C" void kernel_launch(void* const* d_in, const int* in_sizes, int n_in,
                              void* d_out, int out_size)
{
    (void)in_sizes; (void)n_in; (void)out_size;
    const int*   idx  = (const int*)  d_in[0];
    const float* wte  = (const float*)d_in[1];
    const float* wpe  = (const float*)d_in[2];
    const float* Wq   = (const float*)d_in[3];
    const float* Wk   = (const float*)d_in[4];
    const float* Wv   = (const float*)d_in[5];
    const float* Wo   = (const float*)d_in[6];
    const float* ln1g = (const float*)d_in[7];
    const float* ln1b = (const float*)d_in[8];
    const float* ln2g = (const float*)d_in[9];
    const float* ln2b = (const float*)d_in[10];
    const float* W1   = (const float*)d_in[11];
    const float* b1   = (const float*)d_in[12];
    const float* W2   = (const float*)d_in[13];
    const float* b2   = (const float*)d_in[14];
    const float* lnfg = (const float*)d_in[15];
    const float* lnfb = (const float*)d_in[16];
    float* out = (float*)d_out;

    float *x, *h, *q, *k, *v, *o, *f, *s;
    cudaGetSymbolAddress((void**)&x, g_x);
    cudaGetSymbolAddress((void**)&h, g_h);
    cudaGetSymbolAddress((void**)&q, g_q);
    cudaGetSymbolAddress((void**)&k, g_k);
    cudaGetSymbolAddress((void**)&v, g_v);
    cudaGetSymbolAddress((void**)&o, g_o);
    cudaGetSymbolAddress((void**)&f, g_f);
    cudaGetSymbolAddress((void**)&s, g_s);

    // embedding
    embed_kernel<<<(MM * EE) / 256, 256>>>(idx, wte, wpe, x);

    const long long EE2 = (long long)EE * EE;
    const long long TE  = (long long)TT * EE;
    const long long T2  = (long long)TT * TT;

    for (int l = 0; l < LL; l++) {
        // ln1
        ln_kernel<<<MM, 256>>>(x, ln1g + (long long)l * EE, ln1b + (long long)l * EE, h);

        // q,k,v projections (M=4096, N=1024, K=1024)
        gemm(h, Wq + l * EE2, nullptr, q, MM, EE, EE, EE, EE, EE, false,
             1, 1, 0, 0, 0, 0, 0, 0, 0, 1.0f, 0);
        gemm(h, Wk + l * EE2, nullptr, k, MM, EE, EE, EE, EE, EE, false,
             1, 1, 0, 0, 0, 0, 0, 0, 0, 1.0f, 0);
        gemm(h, Wv + l * EE2, nullptr, v, MM, EE, EE, EE, EE, EE, false,
             1, 1, 0, 0, 0, 0, 0, 0, 0, 1.0f, 0);

        // scores: S[b,h] = Q_slice @ K_slice^T * 1/sqrt(D), causal block skip
        gemm(q, k, nullptr, s, TT, TT, DD, EE, EE, TT, true,
             BB * HH, HH,
             TE, DD, TE, DD, (long long)HH * T2, T2,
             0, 0.125f, 1);

        // causal softmax
        { dim3 g2(TT, BB * HH); softmax_kernel<<<g2, 256>>>(s); }

        // O = softmax(S) @ V_slice
        gemm(s, v, nullptr, o, TT, DD, TT, TT, EE, EE, false,
             BB * HH, HH,
             (long long)HH * T2, T2, TE, DD, TE, DD,
             0, 1.0f, 0);

        // x += O @ Wo
        gemm(o, Wo + l * EE2, nullptr, x, MM, EE, EE, EE, EE, EE, false,
             1, 1, 0, 0, 0, 0, 0, 0, 3, 1.0f, 0);

        // ln2
        ln_kernel<<<MM, 256>>>(x, ln2g + (long long)l * EE, ln2b + (long long)l * EE, h);

        // f = gelu(h @ W1 + b1)
        gemm(h, W1 + (long long)l * EE * FF, b1 + (long long)l * FF, f,
             MM, FF, EE, EE, FF, FF, false,
             1, 1, 0, 0, 0, 0, 0, 0, 1, 1.0f, 0);

        // x += f @ W2 + b2
        gemm(f, W2 + (long long)l * FF * EE, b2 + (long long)l * EE, x,
             MM, EE, FF, FF, EE, EE, false,
             1, 1, 0, 0, 0, 0, 0, 0, 2, 1.0f, 0);
    }

    // final LN
    ln_kernel<<<MM, 256>>>(x, lnfg, lnfb, h);

    // logits = h @ wte^T   (M=4096, N=32000, K=1024)
    gemm(h, wte, nullptr, out, MM, VV, EE, EE, EE, VV, true,
         1, 1, 0, 0, 0, 0, 0, 0, 0, 1.0f, 0);
}

// round 2
// speedup vs baseline: 2.2212x; 2.2212x over previous
#include <cuda_runtime.h>
#include <cuda_bf16.h>
#include <math.h>
#include <stdint.h>

// Problem constants
#define BB 4
#define TT 1024
#define EE 1024
#define HH 16
#define DD 64
#define FF 4096
#define LL 6
#define VV 32000
#define MM (BB*TT)
#define LN_EPS 1e-5f

// ---------------------------------------------------------------------------
// Scratch (device globals; no cudaMalloc allowed)
// ---------------------------------------------------------------------------
__device__ float g_x[(size_t)MM * EE];
__device__ float g_h[(size_t)MM * EE];
__device__ float g_q[(size_t)MM * EE];
__device__ float g_k[(size_t)MM * EE];
__device__ float g_v[(size_t)MM * EE];
__device__ float g_o[(size_t)MM * EE];
__device__ float g_f[(size_t)MM * FF];
__device__ float g_s[(size_t)BB * HH * TT * TT];

// ---------------------------------------------------------------------------
// Embedding
// ---------------------------------------------------------------------------
__global__ void embed_kernel(const int* __restrict__ idx,
                             const float* __restrict__ wte,
                             const float* __restrict__ wpe,
                             float* __restrict__ x)
{
    long long i = (long long)blockIdx.x * blockDim.x + threadIdx.x;
    int bt = (int)(i >> 10);
    int e  = (int)(i & 1023);
    int t  = bt & (TT - 1);
    x[i] = wte[(long long)idx[bt] * EE + e] + wpe[(long long)t * EE + e];
}

// ---------------------------------------------------------------------------
// LayerNorm
// ---------------------------------------------------------------------------
__device__ __forceinline__ float warp_sum(float v) {
    #pragma unroll
    for (int o = 16; o > 0; o >>= 1) v += __shfl_xor_sync(0xffffffffu, v, o);
    return v;
}

__global__ __launch_bounds__(256) void ln_kernel(const float* __restrict__ x,
                                                 const float* __restrict__ gamma,
                                                 const float* __restrict__ beta,
                                                 float* __restrict__ out)
{
    int row = blockIdx.x;
    const float* xr = x + (long long)row * EE;
    float* orow = out + (long long)row * EE;
    int tid = threadIdx.x;

    float s = 0.f, s2 = 0.f;
    float vals[4];
    #pragma unroll
    for (int u = 0; u < 4; u++) {
        float v = xr[tid + u * 256];
        vals[u] = v;
        s += v; s2 += v * v;
    }
    s  = warp_sum(s);
    s2 = warp_sum(s2);
    __shared__ float shs[8], shs2[8];
    int wid = tid >> 5, lane = tid & 31;
    if (lane == 0) { shs[wid] = s; shs2[wid] = s2; }
    __syncthreads();
    float ts = 0.f, ts2 = 0.f;
    #pragma unroll
    for (int i = 0; i < 8; i++) { ts += shs[i]; ts2 += shs2[i]; }
    float mean = ts * (1.0f / EE);
    float var  = ts2 * (1.0f / EE) - mean * mean;
    float rstd = rsqrtf(var + LN_EPS);
    #pragma unroll
    for (int u = 0; u < 4; u++) {
        int j = tid + u * 256;
        orow[j] = (vals[u] - mean) * rstd * gamma[j] + beta[j];
    }
}

// ---------------------------------------------------------------------------
// Causal softmax
// ---------------------------------------------------------------------------
__global__ __launch_bounds__(256) void softmax_kernel(float* __restrict__ S)
{
    int t  = blockIdx.x;
    int bh = blockIdx.y;
    float* row = S + ((long long)bh * TT + t) * (long long)TT;
    int tid = threadIdx.x;

    __shared__ float sh[8];
    int wid = tid >> 5, lane = tid & 31;

    float mx = -INFINITY;
    for (int j = tid; j <= t; j += 256) mx = fmaxf(mx, row[j]);
    #pragma unroll
    for (int o = 16; o > 0; o >>= 1) mx = fmaxf(mx, __shfl_xor_sync(0xffffffffu, mx, o));
    if (lane == 0) sh[wid] = mx;
    __syncthreads();
    float m = sh[0];
    #pragma unroll
    for (int i = 1; i < 8; i++) m = fmaxf(m, sh[i]);
    __syncthreads();

    float sum = 0.f;
    for (int j = tid; j < TT; j += 256) {
        float e = (j <= t) ? __expf(row[j] - m) : 0.f;
        row[j] = e;
        sum += e;
    }
    sum = warp_sum(sum);
    if (lane == 0) sh[wid] = sum;
    __syncthreads();
    float tot = 0.f;
    #pragma unroll
    for (int i = 0; i < 8; i++) tot += sh[i];
    float inv = 1.0f / tot;
    for (int j = tid; j <= t; j += 256) row[j] *= inv;
}

// ---------------------------------------------------------------------------
// Tensor-core tf32 GEMM.  C[M,N] = epi( alpha * A @ B(^T) )
// BM=128 fixed, BK=16, BN template (128 or 64). 256 threads, 8 warps,
// warp grid 2(M) x 4(N): warp tile 64 x (BN/4). mma.m16n8k8 tf32.
// ---------------------------------------------------------------------------
#define BM 128
#define BK 16

__device__ __forceinline__ float tf32r(float x) {
    uint32_t u;
    asm("cvt.rna.tf32.f32 %0, %1;" : "=r"(u) : "f"(x));
    return __uint_as_float(u);
}

__device__ __forceinline__ void mma_tf32(float* c, const uint32_t* a, const uint32_t* b) {
    asm volatile(
        "mma.sync.aligned.m16n8k8.row.col.f32.tf32.tf32.f32 "
        "{%0,%1,%2,%3}, {%4,%5,%6,%7}, {%8,%9}, {%0,%1,%2,%3};\n"
        : "+f"(c[0]), "+f"(c[1]), "+f"(c[2]), "+f"(c[3])
        : "r"(a[0]), "r"(a[1]), "r"(a[2]), "r"(a[3]), "r"(b[0]), "r"(b[1]));
}

template<int BN, bool TB>
__global__ __launch_bounds__(256) void gemm_tc(
    const float* __restrict__ A, const float* __restrict__ Bm,
    const float* __restrict__ bias, float* __restrict__ C,
    int M, int N, int K, int lda, int ldb, int ldc,
    int nh,
    long long sAo, long long sAi, long long sBo, long long sBi,
    long long sCo, long long sCi,
    int epi, float alpha, int causal)
{
    int z = blockIdx.z;
    A  += (long long)(z / nh) * sAo + (long long)(z % nh) * sAi;
    Bm += (long long)(z / nh) * sBo + (long long)(z % nh) * sBi;
    C  += (long long)(z / nh) * sCo + (long long)(z % nh) * sCi;

    int n0 = blockIdx.x * BN;
    int m0 = blockIdx.y * BM;
    if (causal && n0 > m0 + BM - 1) return;

    __shared__ float As[BK][BM + 4];
    __shared__ float Bs[BK][BN + 4];

    int tid  = threadIdx.x;
    int warp = tid >> 5, lane = tid & 31;
    int g  = lane >> 2;          // group id 0..7
    int tg = lane & 3;           // thread in group
    int warp_m = warp >> 2;      // 0..1
    int warp_n = warp & 3;       // 0..3
    constexpr int NF = BN / 32;  // n-frags per warp (4 or 2)
    constexpr int WN = BN / 4;   // warp n-tile width

    float acc[4][NF][4];
    #pragma unroll
    for (int i = 0; i < 4; i++)
        #pragma unroll
        for (int j = 0; j < NF; j++)
            #pragma unroll
            for (int c = 0; c < 4; c++) acc[i][j][c] = 0.f;

    for (int k0 = 0; k0 < K; k0 += BK) {
        // ---- load A tile: 128x16 = 512 float4, 2 per thread ----
        #pragma unroll
        for (int i = 0; i < 2; i++) {
            int idx = tid + i * 256;
            int row = idx >> 2;
            int kq  = (idx & 3) << 2;
            float4 a = *(const float4*)(A + (long long)(m0 + row) * lda + k0 + kq);
            As[kq + 0][row] = tf32r(a.x);
            As[kq + 1][row] = tf32r(a.y);
            As[kq + 2][row] = tf32r(a.z);
            As[kq + 3][row] = tf32r(a.w);
        }
        // ---- load B tile ----
        if (!TB) {
            constexpr int F4  = BN / 4;
            constexpr int CNT = (BK * F4) / 256;
            #pragma unroll
            for (int i = 0; i < CNT; i++) {
                int idx = tid + i * 256;
                int row = idx / F4;
                int c   = (idx % F4) << 2;
                float4 b = *(const float4*)(Bm + (long long)(k0 + row) * ldb + n0 + c);
                Bs[row][c + 0] = tf32r(b.x);
                Bs[row][c + 1] = tf32r(b.y);
                Bs[row][c + 2] = tf32r(b.z);
                Bs[row][c + 3] = tf32r(b.w);
            }
        } else {
            constexpr int CNT = (BN * 4) / 256;
            #pragma unroll
            for (int i = 0; i < CNT; i++) {
                int idx = tid + i * 256;
                int row = idx >> 2;       // n
                int kq  = (idx & 3) << 2; // k
                float4 b = *(const float4*)(Bm + (long long)(n0 + row) * ldb + k0 + kq);
                Bs[kq + 0][row] = tf32r(b.x);
                Bs[kq + 1][row] = tf32r(b.y);
                Bs[kq + 2][row] = tf32r(b.z);
                Bs[kq + 3][row] = tf32r(b.w);
            }
        }
        __syncthreads();

        // ---- mma over 2 k-steps of 8 ----
        #pragma unroll
        for (int ks = 0; ks < BK; ks += 8) {
            uint32_t afr[4][4];
            #pragma unroll
            for (int mi = 0; mi < 4; mi++) {
                int mb = warp_m * 64 + mi * 16 + g;
                afr[mi][0] = __float_as_uint(As[ks + tg    ][mb    ]);
                afr[mi][1] = __float_as_uint(As[ks + tg    ][mb + 8]);
                afr[mi][2] = __float_as_uint(As[ks + tg + 4][mb    ]);
                afr[mi][3] = __float_as_uint(As[ks + tg + 4][mb + 8]);
            }
            uint32_t bfr[NF][2];
            #pragma unroll
            for (int ni = 0; ni < NF; ni++) {
                int nb = warp_n * WN + ni * 8 + g;
                bfr[ni][0] = __float_as_uint(Bs[ks + tg    ][nb]);
                bfr[ni][1] = __float_as_uint(Bs[ks + tg + 4][nb]);
            }
            #pragma unroll
            for (int mi = 0; mi < 4; mi++)
                #pragma unroll
                for (int ni = 0; ni < NF; ni++)
                    mma_tf32(acc[mi][ni], afr[mi], bfr[ni]);
        }
        __syncthreads();
    }

    // ---- epilogue ----
    #pragma unroll
    for (int mi = 0; mi < 4; mi++) {
        #pragma unroll
        for (int ni = 0; ni < NF; ni++) {
            int r0 = m0 + warp_m * 64 + mi * 16 + g;
            int c0 = n0 + warp_n * WN + ni * 8 + 2 * tg;
            #pragma unroll
            for (int cc = 0; cc < 4; cc++) {
                int m = r0 + (cc >> 1) * 8;
                int n = c0 + (cc & 1);
                float v = acc[mi][ni][cc] * alpha;
                long long ci = (long long)m * ldc + n;
                if (epi == 1) {
                    v += bias[n];
                    v = 0.5f * v * (1.0f + erff(v * 0.70710678118654752f));
                } else if (epi == 2) {
                    v += bias[n] + C[ci];
                } else if (epi == 3) {
                    v += C[ci];
                }
                C[ci] = v;
            }
        }
    }
}

// ---------------------------------------------------------------------------
// Host-side launch helper
// ---------------------------------------------------------------------------
static inline void gemm(const float* A, const float* B, const float* bias, float* C,
                        int M, int N, int K, int lda, int ldb, int ldc, bool tb,
                        int batch, int nh,
                        long long sAo, long long sAi, long long sBo, long long sBi,
                        long long sCo, long long sCi,
                        int epi, float alpha, int causal)
{
    dim3 block(256);
    if (N % 128 == 0) {
        dim3 grid(N / 128, M / BM, batch);
        if (tb)
            gemm_tc<128, true><<<grid, block>>>(A, B, bias, C, M, N, K, lda, ldb, ldc,
                                                nh, sAo, sAi, sBo, sBi, sCo, sCi, epi, alpha, causal);
        else
            gemm_tc<128, false><<<grid, block>>>(A, B, bias, C, M, N, K, lda, ldb, ldc,
                                                 nh, sAo, sAi, sBo, sBi, sCo, sCi, epi, alpha, causal);
    } else {
        dim3 grid(N / 64, M / BM, batch);
        if (tb)
            gemm_tc<64, true><<<grid, block>>>(A, B, bias, C, M, N, K, lda, ldb, ldc,
                                               nh, sAo, sAi, sBo, sBi, sCo, sCi, epi, alpha, causal);
        else
            gemm_tc<64, false><<<grid, block>>>(A, B, bias, C, M, N, K, lda, ldb, ldc,
                                                nh, sAo, sAi, sBo, sBi, sCo, sCi, epi, alpha, causal);
    }
}

extern "C" void kernel_launch(void* const* d_in, const int* in_sizes, int n_in,
                              void* d_out, int out_size)
{
    (void)in_sizes; (void)n_in; (void)out_size;
    const int*   idx  = (const int*)  d_in[0];
    const float* wte  = (const float*)d_in[1];
    const float* wpe  = (const float*)d_in[2];
    const float* Wq   = (const float*)d_in[3];
    const float* Wk   = (const float*)d_in[4];
    const float* Wv   = (const float*)d_in[5];
    const float* Wo   = (const float*)d_in[6];
    const float* ln1g = (const float*)d_in[7];
    const float* ln1b = (const float*)d_in[8];
    const float* ln2g = (const float*)d_in[9];
    const float* ln2b = (const float*)d_in[10];
    const float* W1   = (const float*)d_in[11];
    const float* b1   = (const float*)d_in[12];
    const float* W2   = (const float*)d_in[13];
    const float* b2   = (const float*)d_in[14];
    const float* lnfg = (const float*)d_in[15];
    const float* lnfb = (const float*)d_in[16];
    float* out = (float*)d_out;

    float *x, *h, *q, *k, *v, *o, *f, *s;
    cudaGetSymbolAddress((void**)&x, g_x);
    cudaGetSymbolAddress((void**)&h, g_h);
    cudaGetSymbolAddress((void**)&q, g_q);
    cudaGetSymbolAddress((void**)&k, g_k);
    cudaGetSymbolAddress((void**)&v, g_v);
    cudaGetSymbolAddress((void**)&o, g_o);
    cudaGetSymbolAddress((void**)&f, g_f);
    cudaGetSymbolAddress((void**)&s, g_s);

    embed_kernel<<<(MM * EE) / 256, 256>>>(idx, wte, wpe, x);

    const long long EE2 = (long long)EE * EE;
    const long long TE  = (long long)TT * EE;
    const long long T2  = (long long)TT * TT;

    for (int l = 0; l < LL; l++) {
        ln_kernel<<<MM, 256>>>(x, ln1g + (long long)l * EE, ln1b + (long long)l * EE, h);

        gemm(h, Wq + l * EE2, nullptr, q, MM, EE, EE, EE, EE, EE, false,
             1, 1, 0, 0, 0, 0, 0, 0, 0, 1.0f, 0);
        gemm(h, Wk + l * EE2, nullptr, k, MM, EE, EE, EE, EE, EE, false,
             1, 1, 0, 0, 0, 0, 0, 0, 0, 1.0f, 0);
        gemm(h, Wv + l * EE2, nullptr, v, MM, EE, EE, EE, EE, EE, false,
             1, 1, 0, 0, 0, 0, 0, 0, 0, 1.0f, 0);

        // scores: S[b,h] = Q @ K^T * 1/8 (causal block skip)
        gemm(q, k, nullptr, s, TT, TT, DD, EE, EE, TT, true,
             BB * HH, HH,
             TE, DD, TE, DD, (long long)HH * T2, T2,
             0, 0.125f, 1);

        { dim3 g2(TT, BB * HH); softmax_kernel<<<g2, 256>>>(s); }

        // O = P @ V (N = 64 path)
        gemm(s, v, nullptr, o, TT, DD, TT, TT, EE, EE, false,
             BB * HH, HH,
             (long long)HH * T2, T2, TE, DD, TE, DD,
             0, 1.0f, 0);

        gemm(o, Wo + l * EE2, nullptr, x, MM, EE, EE, EE, EE, EE, false,
             1, 1, 0, 0, 0, 0, 0, 0, 3, 1.0f, 0);

        ln_kernel<<<MM, 256>>>(x, ln2g + (long long)l * EE, ln2b + (long long)l * EE, h);

        gemm(h, W1 + (long long)l * EE * FF, b1 + (long long)l * FF, f,
             MM, FF, EE, EE, FF, FF, false,
             1, 1, 0, 0, 0, 0, 0, 0, 1, 1.0f, 0);

        gemm(f, W2 + (long long)l * FF * EE, b2 + (long long)l * EE, x,
             MM, EE, FF, FF, EE, EE, false,
             1, 1, 0, 0, 0, 0, 0, 0, 2, 1.0f, 0);
    }

    ln_kernel<<<MM, 256>>>(x, lnfg, lnfb, h);

    gemm(h, wte, nullptr, out, MM, VV, EE, EE, EE, VV, true,
         1, 1, 0, 0, 0, 0, 0, 0, 0, 1.0f, 0);
}

// round 3
// speedup vs baseline: 2.2235x; 1.0010x over previous
#include <cuda_runtime.h>
#include <cuda_bf16.h>
#include <math.h>
#include <stdint.h>

// Problem constants
#define BB 4
#define TT 1024
#define EE 1024
#define HH 16
#define DD 64
#define FF 4096
#define LL 6
#define VV 32000
#define MM (BB*TT)
#define LN_EPS 1e-5f

// ---------------------------------------------------------------------------
// Scratch (device globals; no cudaMalloc allowed)
// ---------------------------------------------------------------------------
__device__ float g_x[(size_t)MM * EE];
__device__ float g_h[(size_t)MM * EE];
__device__ float g_q[(size_t)MM * EE];
__device__ float g_k[(size_t)MM * EE];
__device__ float g_v[(size_t)MM * EE];
__device__ float g_o[(size_t)MM * EE];
__device__ float g_f[(size_t)MM * FF];
__device__ float g_s[(size_t)BB * HH * TT * TT];

// ---------------------------------------------------------------------------
// Embedding
// ---------------------------------------------------------------------------
__global__ void embed_kernel(const int* __restrict__ idx,
                             const float* __restrict__ wte,
                             const float* __restrict__ wpe,
                             float* __restrict__ x)
{
    long long i = (long long)blockIdx.x * blockDim.x + threadIdx.x;
    int bt = (int)(i >> 10);
    int e  = (int)(i & 1023);
    int t  = bt & (TT - 1);
    x[i] = wte[(long long)idx[bt] * EE + e] + wpe[(long long)t * EE + e];
}

// ---------------------------------------------------------------------------
// LayerNorm
// ---------------------------------------------------------------------------
__device__ __forceinline__ float warp_sum(float v) {
    #pragma unroll
    for (int o = 16; o > 0; o >>= 1) v += __shfl_xor_sync(0xffffffffu, v, o);
    return v;
}

__global__ __launch_bounds__(256) void ln_kernel(const float* __restrict__ x,
                                                 const float* __restrict__ gamma,
                                                 const float* __restrict__ beta,
                                                 float* __restrict__ out)
{
    int row = blockIdx.x;
    const float* xr = x + (long long)row * EE;
    float* orow = out + (long long)row * EE;
    int tid = threadIdx.x;

    float s = 0.f, s2 = 0.f;
    float vals[4];
    #pragma unroll
    for (int u = 0; u < 4; u++) {
        float v = xr[tid + u * 256];
        vals[u] = v;
        s += v; s2 += v * v;
    }
    s  = warp_sum(s);
    s2 = warp_sum(s2);
    __shared__ float shs[8], shs2[8];
    int wid = tid >> 5, lane = tid & 31;
    if (lane == 0) { shs[wid] = s; shs2[wid] = s2; }
    __syncthreads();
    float ts = 0.f, ts2 = 0.f;
    #pragma unroll
    for (int i = 0; i < 8; i++) { ts += shs[i]; ts2 += shs2[i]; }
    float mean = ts * (1.0f / EE);
    float var  = ts2 * (1.0f / EE) - mean * mean;
    float rstd = rsqrtf(var + LN_EPS);
    #pragma unroll
    for (int u = 0; u < 4; u++) {
        int j = tid + u * 256;
        orow[j] = (vals[u] - mean) * rstd * gamma[j] + beta[j];
    }
}

// ---------------------------------------------------------------------------
// Causal softmax
// ---------------------------------------------------------------------------
__global__ __launch_bounds__(256) void softmax_kernel(float* __restrict__ S)
{
    int t  = blockIdx.x;
    int bh = blockIdx.y;
    float* row = S + ((long long)bh * TT + t) * (long long)TT;
    int tid = threadIdx.x;

    __shared__ float sh[8];
    int wid = tid >> 5, lane = tid & 31;

    float mx = -INFINITY;
    for (int j = tid; j <= t; j += 256) mx = fmaxf(mx, row[j]);
    #pragma unroll
    for (int o = 16; o > 0; o >>= 1) mx = fmaxf(mx, __shfl_xor_sync(0xffffffffu, mx, o));
    if (lane == 0) sh[wid] = mx;
    __syncthreads();
    float m = sh[0];
    #pragma unroll
    for (int i = 1; i < 8; i++) m = fmaxf(m, sh[i]);
    __syncthreads();

    float sum = 0.f;
    for (int j = tid; j < TT; j += 256) {
        float e = (j <= t) ? __expf(row[j] - m) : 0.f;
        row[j] = e;
        sum += e;
    }
    sum = warp_sum(sum);
    if (lane == 0) sh[wid] = sum;
    __syncthreads();
    float tot = 0.f;
    #pragma unroll
    for (int i = 0; i < 8; i++) tot += sh[i];
    float inv = 1.0f / tot;
    for (int j = tid; j <= t; j += 256) row[j] *= inv;
}

// ---------------------------------------------------------------------------
// Tensor-core tf32 GEMM.  C[M,N] = epi( alpha * A @ B(^T) )
// BM=128 fixed, BK=16, BN template (128 or 64). 256 threads, 8 warps,
// warp grid 2(M) x 4(N): warp tile 64 x (BN/4). mma.m16n8k8 tf32.
// ---------------------------------------------------------------------------
#define BM 128
#define BK 16

__device__ __forceinline__ float tf32r(float x) {
    uint32_t u;
    asm("cvt.rna.tf32.f32 %0, %1;" : "=r"(u) : "f"(x));
    return __uint_as_float(u);
}

__device__ __forceinline__ void mma_tf32(float* c, const uint32_t* a, const uint32_t* b) {
    asm volatile(
        "mma.sync.aligned.m16n8k8.row.col.f32.tf32.tf32.f32 "
        "{%0,%1,%2,%3}, {%4,%5,%6,%7}, {%8,%9}, {%0,%1,%2,%3};\n"
        : "+f"(c[0]), "+f"(c[1]), "+f"(c[2]), "+f"(c[3])
        : "r"(a[0]), "r"(a[1]), "r"(a[2]), "r"(a[3]), "r"(b[0]), "r"(b[1]));
}

template<int BN, bool TB>
__global__ __launch_bounds__(256) void gemm_tc(
    const float* __restrict__ A, const float* __restrict__ Bm,
    const float* __restrict__ bias, float* __restrict__ C,
    int M, int N, int K, int lda, int ldb, int ldc,
    int nh,
    long long sAo, long long sAi, long long sBo, long long sBi,
    long long sCo, long long sCi,
    int epi, float alpha, int causal)
{
    int z = blockIdx.z;
    A  += (long long)(z / nh) * sAo + (long long)(z % nh) * sAi;
    Bm += (long long)(z / nh) * sBo + (long long)(z % nh) * sBi;
    C  += (long long)(z / nh) * sCo + (long long)(z % nh) * sCi;

    int n0 = blockIdx.x * BN;
    int m0 = blockIdx.y * BM;
    if (causal && n0 > m0 + BM - 1) return;

    __shared__ float As[BK][BM + 4];
    __shared__ float Bs[BK][BN + 4];

    int tid  = threadIdx.x;
    int warp = tid >> 5, lane = tid & 31;
    int g  = lane >> 2;          // group id 0..7
    int tg = lane & 3;           // thread in group
    int warp_m = warp >> 2;      // 0..1
    int warp_n = warp & 3;       // 0..3
    constexpr int NF = BN / 32;  // n-frags per warp (4 or 2)
    constexpr int WN = BN / 4;   // warp n-tile width

    float acc[4][NF][4];
    #pragma unroll
    for (int i = 0; i < 4; i++)
        #pragma unroll
        for (int j = 0; j < NF; j++)
            #pragma unroll
            for (int c = 0; c < 4; c++) acc[i][j][c] = 0.f;

    for (int k0 = 0; k0 < K; k0 += BK) {
        // ---- load A tile: 128x16 = 512 float4, 2 per thread ----
        #pragma unroll
        for (int i = 0; i < 2; i++) {
            int idx = tid + i * 256;
            int row = idx >> 2;
            int kq  = (idx & 3) << 2;
            float4 a = *(const float4*)(A + (long long)(m0 + row) * lda + k0 + kq);
            As[kq + 0][row] = tf32r(a.x);
            As[kq + 1][row] = tf32r(a.y);
            As[kq + 2][row] = tf32r(a.z);
            As[kq + 3][row] = tf32r(a.w);
        }
        // ---- load B tile ----
        if (!TB) {
            constexpr int F4  = BN / 4;
            constexpr int CNT = (BK * F4) / 256;
            #pragma unroll
            for (int i = 0; i < CNT; i++) {
                int idx = tid + i * 256;
                int row = idx / F4;
                int c   = (idx % F4) << 2;
                float4 b = *(const float4*)(Bm + (long long)(k0 + row) * ldb + n0 + c);
                Bs[row][c + 0] = tf32r(b.x);
                Bs[row][c + 1] = tf32r(b.y);
                Bs[row][c + 2] = tf32r(b.z);
                Bs[row][c + 3] = tf32r(b.w);
            }
        } else {
            constexpr int CNT = (BN * 4) / 256;
            #pragma unroll
            for (int i = 0; i < CNT; i++) {
                int idx = tid + i * 256;
                int row = idx >> 2;       // n
                int kq  = (idx & 3) << 2; // k
                float4 b = *(const float4*)(Bm + (long long)(n0 + row) * ldb + k0 + kq);
                Bs[kq + 0][row] = tf32r(b.x);
                Bs[kq + 1][row] = tf32r(b.y);
                Bs[kq + 2][row] = tf32r(b.z);
                Bs[kq + 3][row] = tf32r(b.w);
            }
        }
        __syncthreads();

        // ---- mma over 2 k-steps of 8 ----
        #pragma unroll
        for (int ks = 0; ks < BK; ks += 8) {
            uint32_t afr[4][4];
            #pragma unroll
            for (int mi = 0; mi < 4; mi++) {
                int mb = warp_m * 64 + mi * 16 + g;
                afr[mi][0] = __float_as_uint(As[ks + tg    ][mb    ]);
                afr[mi][1] = __float_as_uint(As[ks + tg    ][mb + 8]);
                afr[mi][2] = __float_as_uint(As[ks + tg + 4][mb    ]);
                afr[mi][3] = __float_as_uint(As[ks + tg + 4][mb + 8]);
            }
            uint32_t bfr[NF][2];
            #pragma unroll
            for (int ni = 0; ni < NF; ni++) {
                int nb = warp_n * WN + ni * 8 + g;
                bfr[ni][0] = __float_as_uint(Bs[ks + tg    ][nb]);
                bfr[ni][1] = __float_as_uint(Bs[ks + tg + 4][nb]);
            }
            #pragma unroll
            for (int mi = 0; mi < 4; mi++)
                #pragma unroll
                for (int ni = 0; ni < NF; ni++)
                    mma_tf32(acc[mi][ni], afr[mi], bfr[ni]);
        }
        __syncthreads();
    }

    // ---- epilogue ----
    #pragma unroll
    for (int mi = 0; mi < 4; mi++) {
        #pragma unroll
        for (int ni = 0; ni < NF; ni++) {
            int r0 = m0 + warp_m * 64 + mi * 16 + g;
            int c0 = n0 + warp_n * WN + ni * 8 + 2 * tg;
            #pragma unroll
            for (int cc = 0; cc < 4; cc++) {
                int m = r0 + (cc >> 1) * 8;
                int n = c0 + (cc & 1);
                float v = acc[mi][ni][cc] * alpha;
                long long ci = (long long)m * ldc + n;
                if (epi == 1) {
                    v += bias[n];
                    v = 0.5f * v * (1.0f + erff(v * 0.70710678118654752f));
                } else if (epi == 2) {
                    v += bias[n] + C[ci];
                } else if (epi == 3) {
                    v += C[ci];
                }
                C[ci] = v;
            }
        }
    }
}

// ---------------------------------------------------------------------------
// Host-side launch helper
// ---------------------------------------------------------------------------
static inline void gemm(const float* A, const float* B, const float* bias, float* C,
                        int M, int N, int K, int lda, int ldb, int ldc, bool tb,
                        int batch, int nh,
                        long long sAo, long long sAi, long long sBo, long long sBi,
                        long long sCo, long long sCi,
                        int epi, float alpha, int causal)
{
    dim3 block(256);
    if (N % 128 == 0) {
        dim3 grid(N / 128, M / BM, batch);
        if (tb)
            gemm_tc<128, true><<<grid, block>>>(A, B, bias, C, M, N, K, lda, ldb, ldc,
                                                nh, sAo, sAi, sBo, sBi, sCo, sCi, epi, alpha, causal);
        else
            gemm_tc<128, false><<<grid, block>>>(A, B, bias, C, M, N, K, lda, ldb, ldc,
                                                 nh, sAo, sAi, sBo, sBi, sCo, sCi, epi, alpha, causal);
    } else {
        dim3 grid(N / 64, M / BM, batch);
        if (tb)
            gemm_tc<64, true><<<grid, block>>>(A, B, bias, C, M, N, K, lda, ldb, ldc,
                                               nh, sAo, sAi, sBo, sBi, sCo, sCi, epi, alpha, causal);
        else
            gemm_tc<64, false><<<grid, block>>>(A, B, bias, C, M, N, K, lda, ldb, ldc,
                                                nh, sAo, sAi, sBo, sBi, sCo, sCi, epi, alpha, causal);
    }
}

extern "C" void kernel_launch(void* const* d_in, const int* in_sizes, int n_in,
                              void* d_out, int out_size)
{
    (void)in_sizes; (void)n_in; (void)out_size;
    const int*   idx  = (const int*)  d_in[0];
    const float* wte  = (const float*)d_in[1];
    const float* wpe  = (const float*)d_in[2];
    const float* Wq   = (const float*)d_in[3];
    const float* Wk   = (const float*)d_in[4];
    const float* Wv   = (const float*)d_in[5];
    const float* Wo   = (const float*)d_in[6];
    const float* ln1g = (const float*)d_in[7];
    const float* ln1b = (const float*)d_in[8];
    const float* ln2g = (const float*)d_in[9];
    const float* ln2b = (const float*)d_in[10];
    const float* W1   = (const float*)d_in[11];
    const float* b1   = (const float*)d_in[12];
    const float* W2   = (const float*)d_in[13];
    const float* b2   = (const float*)d_in[14];
    const float* lnfg = (const float*)d_in[15];
    const float* lnfb = (const float*)d_in[16];
    float* out = (float*)d_out;

    float *x, *h, *q, *k, *v, *o, *f, *s;
    cudaGetSymbolAddress((void**)&x, g_x);
    cudaGetSymbolAddress((void**)&h, g_h);
    cudaGetSymbolAddress((void**)&q, g_q);
    cudaGetSymbolAddress((void**)&k, g_k);
    cudaGetSymbolAddress((void**)&v, g_v);
    cudaGetSymbolAddress((void**)&o, g_o);
    cudaGetSymbolAddress((void**)&f, g_f);
    cudaGetSymbolAddress((void**)&s, g_s);

    embed_kernel<<<(MM * EE) / 256, 256>>>(idx, wte, wpe, x);

    const long long EE2 = (long long)EE * EE;
    const long long TE  = (long long)TT * EE;
    const long long T2  = (long long)TT * TT;

    for (int l = 0; l < LL; l++) {
        ln_kernel<<<MM, 256>>>(x, ln1g + (long long)l * EE, ln1b + (long long)l * EE, h);

        gemm(h, Wq + l * EE2, nullptr, q, MM, EE, EE, EE, EE, EE, false,
             1, 1, 0, 0, 0, 0, 0, 0, 0, 1.0f, 0);
        gemm(h, Wk + l * EE2, nullptr, k, MM, EE, EE, EE, EE, EE, false,
             1, 1, 0, 0, 0, 0, 0, 0, 0, 1.0f, 0);
        gemm(h, Wv + l * EE2, nullptr, v, MM, EE, EE, EE, EE, EE, false,
             1, 1, 0, 0, 0, 0, 0, 0, 0, 1.0f, 0);

        // scores: S[b,h] = Q @ K^T * 1/8 (causal block skip)
        gemm(q, k, nullptr, s, TT, TT, DD, EE, EE, TT, true,
             BB * HH, HH,
             TE, DD, TE, DD, (long long)HH * T2, T2,
             0, 0.125f, 1);

        { dim3 g2(TT, BB * HH); softmax_kernel<<<g2, 256>>>(s); }

        // O = P @ V (N = 64 path)
        gemm(s, v, nullptr, o, TT, DD, TT, TT, EE, EE, false,
             BB * HH, HH,
             (long long)HH * T2, T2, TE, DD, TE, DD,
             0, 1.0f, 0);

        gemm(o, Wo + l * EE2, nullptr, x, MM, EE, EE, EE, EE, EE, false,
             1, 1, 0, 0, 0, 0, 0, 0, 3, 1.0f, 0);

        ln_kernel<<<MM, 256>>>(x, ln2g + (long long)l * EE, ln2b + (long long)l * EE, h);

        gemm(h, W1 + (long long)l * EE * FF, b1 + (long long)l * FF, f,
             MM, FF, EE, EE, FF, FF, false,
             1, 1, 0, 0, 0, 0, 0, 0, 1, 1.0f, 0);

        gemm(f, W2 + (long long)l * FF * EE, b2 + (long long)l * EE, x,
             MM, EE, FF, FF, EE, EE, false,
             1, 1, 0, 0, 0, 0, 0, 0, 2, 1.0f, 0);
    }

    ln_kernel<<<MM, 256>>>(x, lnfg, lnfb, h);

    gemm(h, wte, nullptr, out, MM, VV, EE, EE, EE, VV, true,
         1, 1, 0, 0, 0, 0, 0, 0, 0, 1.0f, 0);
}

// round 4
// speedup vs baseline: 2.2270x; 1.0016x over previous
#include <cuda_runtime.h>
#include <cuda_bf16.h>
#include <math.h>
#include <stdint.h>

// Problem constants
#define BB 4
#define TT 1024
#define EE 1024
#define HH 16
#define DD 64
#define FF 4096
#define LL 6
#define VV 32000
#define MM (BB*TT)
#define LN_EPS 1e-5f

// ---------------------------------------------------------------------------
// Scratch (device globals; no cudaMalloc allowed)
// ---------------------------------------------------------------------------
__device__ float g_x[(size_t)MM * EE];
__device__ float g_h[(size_t)MM * EE];
__device__ float g_q[(size_t)MM * EE];
__device__ float g_k[(size_t)MM * EE];
__device__ float g_v[(size_t)MM * EE];
__device__ float g_o[(size_t)MM * EE];
__device__ float g_f[(size_t)MM * FF];
__device__ float g_s[(size_t)BB * HH * TT * TT];

// ---------------------------------------------------------------------------
// Embedding
// ---------------------------------------------------------------------------
__global__ void embed_kernel(const int* __restrict__ idx,
                             const float* __restrict__ wte,
                             const float* __restrict__ wpe,
                             float* __restrict__ x)
{
    long long i = (long long)blockIdx.x * blockDim.x + threadIdx.x;
    int bt = (int)(i >> 10);
    int e  = (int)(i & 1023);
    int t  = bt & (TT - 1);
    x[i] = wte[(long long)idx[bt] * EE + e] + wpe[(long long)t * EE + e];
}

// ---------------------------------------------------------------------------
// LayerNorm
// ---------------------------------------------------------------------------
__device__ __forceinline__ float warp_sum(float v) {
    #pragma unroll
    for (int o = 16; o > 0; o >>= 1) v += __shfl_xor_sync(0xffffffffu, v, o);
    return v;
}

__global__ __launch_bounds__(256) void ln_kernel(const float* __restrict__ x,
                                                 const float* __restrict__ gamma,
                                                 const float* __restrict__ beta,
                                                 float* __restrict__ out)
{
    int row = blockIdx.x;
    const float* xr = x + (long long)row * EE;
    float* orow = out + (long long)row * EE;
    int tid = threadIdx.x;

    float s = 0.f, s2 = 0.f;
    float vals[4];
    #pragma unroll
    for (int u = 0; u < 4; u++) {
        float v = xr[tid + u * 256];
        vals[u] = v;
        s += v; s2 += v * v;
    }
    s  = warp_sum(s);
    s2 = warp_sum(s2);
    __shared__ float shs[8], shs2[8];
    int wid = tid >> 5, lane = tid & 31;
    if (lane == 0) { shs[wid] = s; shs2[wid] = s2; }
    __syncthreads();
    float ts = 0.f, ts2 = 0.f;
    #pragma unroll
    for (int i = 0; i < 8; i++) { ts += shs[i]; ts2 += shs2[i]; }
    float mean = ts * (1.0f / EE);
    float var  = ts2 * (1.0f / EE) - mean * mean;
    float rstd = rsqrtf(var + LN_EPS);
    #pragma unroll
    for (int u = 0; u < 4; u++) {
        int j = tid + u * 256;
        orow[j] = (vals[u] - mean) * rstd * gamma[j] + beta[j];
    }
}

// ---------------------------------------------------------------------------
// Causal softmax
// ---------------------------------------------------------------------------
__global__ __launch_bounds__(256) void softmax_kernel(float* __restrict__ S)
{
    int t  = blockIdx.x;
    int bh = blockIdx.y;
    float* row = S + ((long long)bh * TT + t) * (long long)TT;
    int tid = threadIdx.x;

    __shared__ float sh[8];
    int wid = tid >> 5, lane = tid & 31;

    float mx = -INFINITY;
    for (int j = tid; j <= t; j += 256) mx = fmaxf(mx, row[j]);
    #pragma unroll
    for (int o = 16; o > 0; o >>= 1) mx = fmaxf(mx, __shfl_xor_sync(0xffffffffu, mx, o));
    if (lane == 0) sh[wid] = mx;
    __syncthreads();
    float m = sh[0];
    #pragma unroll
    for (int i = 1; i < 8; i++) m = fmaxf(m, sh[i]);
    __syncthreads();

    float sum = 0.f;
    for (int j = tid; j < TT; j += 256) {
        float e = (j <= t) ? __expf(row[j] - m) : 0.f;
        row[j] = e;
        sum += e;
    }
    sum = warp_sum(sum);
    if (lane == 0) sh[wid] = sum;
    __syncthreads();
    float tot = 0.f;
    #pragma unroll
    for (int i = 0; i < 8; i++) tot += sh[i];
    float inv = 1.0f / tot;
    for (int j = tid; j <= t; j += 256) row[j] *= inv;
}

// ---------------------------------------------------------------------------
// Tensor-core tf32 GEMM.  C[M,N] = epi( alpha * A @ B(^T) )
// BM=128 fixed, BK=16, BN template (128 or 64). 256 threads, 8 warps,
// warp grid 2(M) x 4(N): warp tile 64 x (BN/4). mma.m16n8k8 tf32.
// ---------------------------------------------------------------------------
#define BM 128
#define BK 16

__device__ __forceinline__ float tf32r(float x) {
    uint32_t u;
    asm("cvt.rna.tf32.f32 %0, %1;" : "=r"(u) : "f"(x));
    return __uint_as_float(u);
}

__device__ __forceinline__ void mma_tf32(float* c, const uint32_t* a, const uint32_t* b) {
    asm volatile(
        "mma.sync.aligned.m16n8k8.row.col.f32.tf32.tf32.f32 "
        "{%0,%1,%2,%3}, {%4,%5,%6,%7}, {%8,%9}, {%0,%1,%2,%3};\n"
        : "+f"(c[0]), "+f"(c[1]), "+f"(c[2]), "+f"(c[3])
        : "r"(a[0]), "r"(a[1]), "r"(a[2]), "r"(a[3]), "r"(b[0]), "r"(b[1]));
}

template<int BN, bool TB>
__global__ __launch_bounds__(256) void gemm_tc(
    const float* __restrict__ A, const float* __restrict__ Bm,
    const float* __restrict__ bias, float* __restrict__ C,
    int M, int N, int K, int lda, int ldb, int ldc,
    int nh,
    long long sAo, long long sAi, long long sBo, long long sBi,
    long long sCo, long long sCi,
    int epi, float alpha, int causal)
{
    int z = blockIdx.z;
    A  += (long long)(z / nh) * sAo + (long long)(z % nh) * sAi;
    Bm += (long long)(z / nh) * sBo + (long long)(z % nh) * sBi;
    C  += (long long)(z / nh) * sCo + (long long)(z % nh) * sCi;

    int n0 = blockIdx.x * BN;
    int m0 = blockIdx.y * BM;
    if (causal && n0 > m0 + BM - 1) return;

    __shared__ float As[BK][BM + 4];
    __shared__ float Bs[BK][BN + 4];

    int tid  = threadIdx.x;
    int warp = tid >> 5, lane = tid & 31;
    int g  = lane >> 2;          // group id 0..7
    int tg = lane & 3;           // thread in group
    int warp_m = warp >> 2;      // 0..1
    int warp_n = warp & 3;       // 0..3
    constexpr int NF = BN / 32;  // n-frags per warp (4 or 2)
    constexpr int WN = BN / 4;   // warp n-tile width

    float acc[4][NF][4];
    #pragma unroll
    for (int i = 0; i < 4; i++)
        #pragma unroll
        for (int j = 0; j < NF; j++)
            #pragma unroll
            for (int c = 0; c < 4; c++) acc[i][j][c] = 0.f;

    for (int k0 = 0; k0 < K; k0 += BK) {
        // ---- load A tile: 128x16 = 512 float4, 2 per thread ----
        #pragma unroll
        for (int i = 0; i < 2; i++) {
            int idx = tid + i * 256;
            int row = idx >> 2;
            int kq  = (idx & 3) << 2;
            float4 a = *(const float4*)(A + (long long)(m0 + row) * lda + k0 + kq);
            As[kq + 0][row] = tf32r(a.x);
            As[kq + 1][row] = tf32r(a.y);
            As[kq + 2][row] = tf32r(a.z);
            As[kq + 3][row] = tf32r(a.w);
        }
        // ---- load B tile ----
        if (!TB) {
            constexpr int F4  = BN / 4;
            constexpr int CNT = (BK * F4) / 256;
            #pragma unroll
            for (int i = 0; i < CNT; i++) {
                int idx = tid + i * 256;
                int row = idx / F4;
                int c   = (idx % F4) << 2;
                float4 b = *(const float4*)(Bm + (long long)(k0 + row) * ldb + n0 + c);
                Bs[row][c + 0] = tf32r(b.x);
                Bs[row][c + 1] = tf32r(b.y);
                Bs[row][c + 2] = tf32r(b.z);
                Bs[row][c + 3] = tf32r(b.w);
            }
        } else {
            constexpr int CNT = (BN * 4) / 256;
            #pragma unroll
            for (int i = 0; i < CNT; i++) {
                int idx = tid + i * 256;
                int row = idx >> 2;       // n
                int kq  = (idx & 3) << 2; // k
                float4 b = *(const float4*)(Bm + (long long)(n0 + row) * ldb + k0 + kq);
                Bs[kq + 0][row] = tf32r(b.x);
                Bs[kq + 1][row] = tf32r(b.y);
                Bs[kq + 2][row] = tf32r(b.z);
                Bs[kq + 3][row] = tf32r(b.w);
            }
        }
        __syncthreads();

        // ---- mma over 2 k-steps of 8 ----
        #pragma unroll
        for (int ks = 0; ks < BK; ks += 8) {
            uint32_t afr[4][4];
            #pragma unroll
            for (int mi = 0; mi < 4; mi++) {
                int mb = warp_m * 64 + mi * 16 + g;
                afr[mi][0] = __float_as_uint(As[ks + tg    ][mb    ]);
                afr[mi][1] = __float_as_uint(As[ks + tg    ][mb + 8]);
                afr[mi][2] = __float_as_uint(As[ks + tg + 4][mb    ]);
                afr[mi][3] = __float_as_uint(As[ks + tg + 4][mb + 8]);
            }
            uint32_t bfr[NF][2];
            #pragma unroll
            for (int ni = 0; ni < NF; ni++) {
                int nb = warp_n * WN + ni * 8 + g;
                bfr[ni][0] = __float_as_uint(Bs[ks + tg    ][nb]);
                bfr[ni][1] = __float_as_uint(Bs[ks + tg + 4][nb]);
            }
            #pragma unroll
            for (int mi = 0; mi < 4; mi++)
                #pragma unroll
                for (int ni = 0; ni < NF; ni++)
                    mma_tf32(acc[mi][ni], afr[mi], bfr[ni]);
        }
        __syncthreads();
    }

    // ---- epilogue ----
    #pragma unroll
    for (int mi = 0; mi < 4; mi++) {
        #pragma unroll
        for (int ni = 0; ni < NF; ni++) {
            int r0 = m0 + warp_m * 64 + mi * 16 + g;
            int c0 = n0 + warp_n * WN + ni * 8 + 2 * tg;
            #pragma unroll
            for (int cc = 0; cc < 4; cc++) {
                int m = r0 + (cc >> 1) * 8;
                int n = c0 + (cc & 1);
                float v = acc[mi][ni][cc] * alpha;
                long long ci = (long long)m * ldc + n;
                if (epi == 1) {
                    v += bias[n];
                    v = 0.5f * v * (1.0f + erff(v * 0.70710678118654752f));
                } else if (epi == 2) {
                    v += bias[n] + C[ci];
                } else if (epi == 3) {
                    v += C[ci];
                }
                C[ci] = v;
            }
        }
    }
}

// ---------------------------------------------------------------------------
// Host-side launch helper
// ---------------------------------------------------------------------------
static inline void gemm(const float* A, const float* B, const float* bias, float* C,
                        int M, int N, int K, int lda, int ldb, int ldc, bool tb,
                        int batch, int nh,
                        long long sAo, long long sAi, long long sBo, long long sBi,
                        long long sCo, long long sCi,
                        int epi, float alpha, int causal)
{
    dim3 block(256);
    if (N % 128 == 0) {
        dim3 grid(N / 128, M / BM, batch);
        if (tb)
            gemm_tc<128, true><<<grid, block>>>(A, B, bias, C, M, N, K, lda, ldb, ldc,
                                                nh, sAo, sAi, sBo, sBi, sCo, sCi, epi, alpha, causal);
        else
            gemm_tc<128, false><<<grid, block>>>(A, B, bias, C, M, N, K, lda, ldb, ldc,
                                                 nh, sAo, sAi, sBo, sBi, sCo, sCi, epi, alpha, causal);
    } else {
        dim3 grid(N / 64, M / BM, batch);
        if (tb)
            gemm_tc<64, true><<<grid, block>>>(A, B, bias, C, M, N, K, lda, ldb, ldc,
                                               nh, sAo, sAi, sBo, sBi, sCo, sCi, epi, alpha, causal);
        else
            gemm_tc<64, false><<<grid, block>>>(A, B, bias, C, M, N, K, lda, ldb, ldc,
                                                nh, sAo, sAi, sBo, sBi, sCo, sCi, epi, alpha, causal);
    }
}

extern "C" void kernel_launch(void* const* d_in, const int* in_sizes, int n_in,
                              void* d_out, int out_size)
{
    (void)in_sizes; (void)n_in; (void)out_size;
    const int*   idx  = (const int*)  d_in[0];
    const float* wte  = (const float*)d_in[1];
    const float* wpe  = (const float*)d_in[2];
    const float* Wq   = (const float*)d_in[3];
    const float* Wk   = (const float*)d_in[4];
    const float* Wv   = (const float*)d_in[5];
    const float* Wo   = (const float*)d_in[6];
    const float* ln1g = (const float*)d_in[7];
    const float* ln1b = (const float*)d_in[8];
    const float* ln2g = (const float*)d_in[9];
    const float* ln2b = (const float*)d_in[10];
    const float* W1   = (const float*)d_in[11];
    const float* b1   = (const float*)d_in[12];
    const float* W2   = (const float*)d_in[13];
    const float* b2   = (const float*)d_in[14];
    const float* lnfg = (const float*)d_in[15];
    const float* lnfb = (const float*)d_in[16];
    float* out = (float*)d_out;

    float *x, *h, *q, *k, *v, *o, *f, *s;
    cudaGetSymbolAddress((void**)&x, g_x);
    cudaGetSymbolAddress((void**)&h, g_h);
    cudaGetSymbolAddress((void**)&q, g_q);
    cudaGetSymbolAddress((void**)&k, g_k);
    cudaGetSymbolAddress((void**)&v, g_v);
    cudaGetSymbolAddress((void**)&o, g_o);
    cudaGetSymbolAddress((void**)&f, g_f);
    cudaGetSymbolAddress((void**)&s, g_s);

    embed_kernel<<<(MM * EE) / 256, 256>>>(idx, wte, wpe, x);

    const long long EE2 = (long long)EE * EE;
    const long long TE  = (long long)TT * EE;
    const long long T2  = (long long)TT * TT;

    for (int l = 0; l < LL; l++) {
        ln_kernel<<<MM, 256>>>(x, ln1g + (long long)l * EE, ln1b + (long long)l * EE, h);

        gemm(h, Wq + l * EE2, nullptr, q, MM, EE, EE, EE, EE, EE, false,
             1, 1, 0, 0, 0, 0, 0, 0, 0, 1.0f, 0);
        gemm(h, Wk + l * EE2, nullptr, k, MM, EE, EE, EE, EE, EE, false,
             1, 1, 0, 0, 0, 0, 0, 0, 0, 1.0f, 0);
        gemm(h, Wv + l * EE2, nullptr, v, MM, EE, EE, EE, EE, EE, false,
             1, 1, 0, 0, 0, 0, 0, 0, 0, 1.0f, 0);

        // scores: S[b,h] = Q @ K^T * 1/8 (causal block skip)
        gemm(q, k, nullptr, s, TT, TT, DD, EE, EE, TT, true,
             BB * HH, HH,
             TE, DD, TE, DD, (long long)HH * T2, T2,
             0, 0.125f, 1);

        { dim3 g2(TT, BB * HH); softmax_kernel<<<g2, 256>>>(s); }

        // O = P @ V (N = 64 path)
        gemm(s, v, nullptr, o, TT, DD, TT, TT, EE, EE, false,
             BB * HH, HH,
             (long long)HH * T2, T2, TE, DD, TE, DD,
             0, 1.0f, 0);

        gemm(o, Wo + l * EE2, nullptr, x, MM, EE, EE, EE, EE, EE, false,
             1, 1, 0, 0, 0, 0, 0, 0, 3, 1.0f, 0);

        ln_kernel<<<MM, 256>>>(x, ln2g + (long long)l * EE, ln2b + (long long)l * EE, h);

        gemm(h, W1 + (long long)l * EE * FF, b1 + (long long)l * FF, f,
             MM, FF, EE, EE, FF, FF, false,
             1, 1, 0, 0, 0, 0, 0, 0, 1, 1.0f, 0);

        gemm(f, W2 + (long long)l * FF * EE, b2 + (long long)l * EE, x,
             MM, EE, FF, FF, EE, EE, false,
             1, 1, 0, 0, 0, 0, 0, 0, 2, 1.0f, 0);
    }

    ln_kernel<<<MM, 256>>>(x, lnfg, lnfb, h);

    gemm(h, wte, nullptr, out, MM, VV, EE, EE, EE, VV, true,
         1, 1, 0, 0, 0, 0, 0, 0, 0, 1.0f, 0);
}

// round 5
// speedup vs baseline: 3.3355x; 1.4978x over previous
#include <cuda_runtime.h>
#include <cuda_bf16.h>
#include <math.h>
#include <stdint.h>

// Problem constants
#define BB 4
#define TT 1024
#define EE 1024
#define HH 16
#define DD 64
#define FF 4096
#define LL 6
#define VV 32000
#define MM (BB*TT)
#define LN_EPS 1e-5f

// ---------------------------------------------------------------------------
// Scratch (device globals; no cudaMalloc allowed)
// ---------------------------------------------------------------------------
__device__ float g_x[(size_t)MM * EE];
__device__ float g_h[(size_t)MM * EE];
__device__ float g_q[(size_t)MM * EE];
__device__ float g_k[(size_t)MM * EE];
__device__ float g_v[(size_t)MM * EE];
__device__ float g_o[(size_t)MM * EE];
__device__ float g_f[(size_t)MM * FF];
__device__ float g_s[(size_t)BB * HH * TT * TT];
// pre-rounded (tf32-in-fp32) weights
__device__ float g_wq[(size_t)LL * EE * EE];
__device__ float g_wk[(size_t)LL * EE * EE];
__device__ float g_wv[(size_t)LL * EE * EE];
__device__ float g_wo[(size_t)LL * EE * EE];
__device__ float g_w1[(size_t)LL * EE * FF];
__device__ float g_w2[(size_t)LL * FF * EE];
__device__ float g_wte[(size_t)VV * EE];

__device__ __forceinline__ float tf32r(float x) {
    uint32_t u;
    asm("cvt.rna.tf32.f32 %0, %1;" : "=r"(u) : "f"(x));
    return __uint_as_float(u);
}

// ---------------------------------------------------------------------------
// Round-copy: out[i] = tf32(in[i])
// ---------------------------------------------------------------------------
__global__ __launch_bounds__(256) void round_copy(const float* __restrict__ in,
                                                  float* __restrict__ out, long long n4)
{
    long long i = (long long)blockIdx.x * 256 + threadIdx.x;
    if (i < n4) {
        float4 v = ((const float4*)in)[i];
        v.x = tf32r(v.x); v.y = tf32r(v.y); v.z = tf32r(v.z); v.w = tf32r(v.w);
        ((float4*)out)[i] = v;
    }
}

// ---------------------------------------------------------------------------
// Embedding (residual stream stays fp32)
// ---------------------------------------------------------------------------
__global__ void embed_kernel(const int* __restrict__ idx,
                             const float* __restrict__ wte,
                             const float* __restrict__ wpe,
                             float* __restrict__ x)
{
    long long i = (long long)blockIdx.x * blockDim.x + threadIdx.x;
    int bt = (int)(i >> 10);
    int e  = (int)(i & 1023);
    int t  = bt & (TT - 1);
    x[i] = wte[(long long)idx[bt] * EE + e] + wpe[(long long)t * EE + e];
}

// ---------------------------------------------------------------------------
// LayerNorm (output pre-rounded to tf32 — it only feeds GEMMs)
// ---------------------------------------------------------------------------
__device__ __forceinline__ float warp_sum(float v) {
    #pragma unroll
    for (int o = 16; o > 0; o >>= 1) v += __shfl_xor_sync(0xffffffffu, v, o);
    return v;
}

__global__ __launch_bounds__(256) void ln_kernel(const float* __restrict__ x,
                                                 const float* __restrict__ gamma,
                                                 const float* __restrict__ beta,
                                                 float* __restrict__ out)
{
    int row = blockIdx.x;
    const float* xr = x + (long long)row * EE;
    float* orow = out + (long long)row * EE;
    int tid = threadIdx.x;

    float s = 0.f, s2 = 0.f;
    float vals[4];
    #pragma unroll
    for (int u = 0; u < 4; u++) {
        float v = xr[tid + u * 256];
        vals[u] = v;
        s += v; s2 += v * v;
    }
    s  = warp_sum(s);
    s2 = warp_sum(s2);
    __shared__ float shs[8], shs2[8];
    int wid = tid >> 5, lane = tid & 31;
    if (lane == 0) { shs[wid] = s; shs2[wid] = s2; }
    __syncthreads();
    float ts = 0.f, ts2 = 0.f;
    #pragma unroll
    for (int i = 0; i < 8; i++) { ts += shs[i]; ts2 += shs2[i]; }
    float mean = ts * (1.0f / EE);
    float var  = ts2 * (1.0f / EE) - mean * mean;
    float rstd = rsqrtf(var + LN_EPS);
    #pragma unroll
    for (int u = 0; u < 4; u++) {
        int j = tid + u * 256;
        orow[j] = tf32r((vals[u] - mean) * rstd * gamma[j] + beta[j]);
    }
}

// ---------------------------------------------------------------------------
// Causal softmax (probs pre-rounded to tf32)
// ---------------------------------------------------------------------------
__global__ __launch_bounds__(256) void softmax_kernel(float* __restrict__ S)
{
    int t  = blockIdx.x;
    int bh = blockIdx.y;
    float* row = S + ((long long)bh * TT + t) * (long long)TT;
    int tid = threadIdx.x;

    __shared__ float sh[8];
    int wid = tid >> 5, lane = tid & 31;

    float mx = -INFINITY;
    for (int j = tid; j <= t; j += 256) mx = fmaxf(mx, row[j]);
    #pragma unroll
    for (int o = 16; o > 0; o >>= 1) mx = fmaxf(mx, __shfl_xor_sync(0xffffffffu, mx, o));
    if (lane == 0) sh[wid] = mx;
    __syncthreads();
    float m = sh[0];
    #pragma unroll
    for (int i = 1; i < 8; i++) m = fmaxf(m, sh[i]);
    __syncthreads();

    float sum = 0.f;
    for (int j = tid; j < TT; j += 256) {
        float e = (j <= t) ? __expf(row[j] - m) : 0.f;
        row[j] = e;
        sum += e;
    }
    sum = warp_sum(sum);
    if (lane == 0) sh[wid] = sum;
    __syncthreads();
    float tot = 0.f;
    #pragma unroll
    for (int i = 0; i < 8; i++) tot += sh[i];
    float inv = 1.0f / tot;
    for (int j = tid; j <= t; j += 256) row[j] = tf32r(row[j] * inv);
}

// ---------------------------------------------------------------------------
// cp.async helpers
// ---------------------------------------------------------------------------
__device__ __forceinline__ void cpa16(uint32_t dst, const float* src) {
    asm volatile("cp.async.cg.shared.global [%0], [%1], 16;" :: "r"(dst), "l"(src));
}
__device__ __forceinline__ void cpa_commit() {
    asm volatile("cp.async.commit_group;");
}
template<int N>
__device__ __forceinline__ void cpa_wait() {
    asm volatile("cp.async.wait_group %0;" :: "n"(N));
}

__device__ __forceinline__ void mma_tf32(float* c, const uint32_t* a, const uint32_t* b) {
    asm volatile(
        "mma.sync.aligned.m16n8k8.row.col.f32.tf32.tf32.f32 "
        "{%0,%1,%2,%3}, {%4,%5,%6,%7}, {%8,%9}, {%0,%1,%2,%3};\n"
        : "+f"(c[0]), "+f"(c[1]), "+f"(c[2]), "+f"(c[3])
        : "r"(a[0]), "r"(a[1]), "r"(a[2]), "r"(a[3]), "r"(b[0]), "r"(b[1]));
}

// ---------------------------------------------------------------------------
// Tensor-core tf32 GEMM, 3-stage cp.async pipeline.
// Inputs must already be tf32-rounded. BM=128, BK=16, BN in {128,64}.
// 256 threads = 8 warps (2 x 4), warp tile 64 x (BN/4), mma m16n8k8.
// smem layouts: A [m][k] stride BK+4; B NN [k][n] stride BN+8; B TB [n][k] stride BK+4.
// epi: 0=store 1=gelu(acc+bias) 2=C+=acc+bias 3=C+=acc ; rnd: tf32-round the store
// causal: skip blocks above diagonal ; trik: cap K at m0+BM (lower-triangular A)
// ---------------------------------------------------------------------------
#define BM 128
#define BK 16
#define NSTG 3

template<int BN, bool TB>
__global__ __launch_bounds__(256) void gemm_tc(
    const float* __restrict__ A, const float* __restrict__ Bm,
    const float* __restrict__ bias, float* __restrict__ C,
    int M, int N, int K, int lda, int ldb, int ldc,
    int nh,
    long long sAo, long long sAi, long long sBo, long long sBi,
    long long sCo, long long sCi,
    int epi, float alpha, int causal, int trik, int rnd)
{
    constexpr int ASZ = BM * (BK + 4);
    constexpr int BSZ = TB ? BN * (BK + 4) : BK * (BN + 8);
    constexpr int ST  = ASZ + BSZ;

    extern __shared__ float sm[];

    int z = blockIdx.z;
    A  += (long long)(z / nh) * sAo + (long long)(z % nh) * sAi;
    Bm += (long long)(z / nh) * sBo + (long long)(z % nh) * sBi;
    C  += (long long)(z / nh) * sCo + (long long)(z % nh) * sCi;

    int n0 = blockIdx.x * BN;
    int m0 = blockIdx.y * BM;
    if (causal && n0 > m0 + BM - 1) return;

    int K_eff = trik ? min(K, m0 + BM) : K;
    int nt = K_eff / BK;

    int tid  = threadIdx.x;
    int warp = tid >> 5, lane = tid & 31;
    int g  = lane >> 2;
    int tg = lane & 3;
    int warp_m = warp >> 2;
    int warp_n = warp & 3;
    constexpr int NF = BN / 32;
    constexpr int WN = BN / 4;

    uint32_t smem_u32 = (uint32_t)__cvta_generic_to_shared(sm);

    // tile loader
    auto load_tiles = [&](int st, int k0) {
        uint32_t sb = smem_u32 + (uint32_t)(st * ST) * 4u;
        #pragma unroll
        for (int i = 0; i < 2; i++) {                 // A: 128x16 = 512 float4
            int idx = tid + i * 256;
            int row = idx >> 2;
            int kc  = (idx & 3) << 2;
            cpa16(sb + (uint32_t)(row * (BK + 4) + kc) * 4u,
                  A + (long long)(m0 + row) * lda + k0 + kc);
        }
        if (!TB) {
            constexpr int CH = (BK * BN / 4) / 256;   // 2 (BN=128) or 1 (BN=64)
            #pragma unroll
            for (int i = 0; i < CH; i++) {
                int idx = tid + i * 256;
                int row = idx / (BN / 4);
                int nc  = (idx % (BN / 4)) << 2;
                cpa16(sb + (uint32_t)(ASZ + row * (BN + 8) + nc) * 4u,
                      Bm + (long long)(k0 + row) * ldb + n0 + nc);
            }
        } else {
            constexpr int CH = (BN * BK / 4) / 256;
            #pragma unroll
            for (int i = 0; i < CH; i++) {
                int idx = tid + i * 256;
                int row = idx >> 2;
                int kc  = (idx & 3) << 2;
                cpa16(sb + (uint32_t)(ASZ + row * (BK + 4) + kc) * 4u,
                      Bm + (long long)(n0 + row) * ldb + k0 + kc);
            }
        }
    };

    float acc[4][NF][4];
    #pragma unroll
    for (int i = 0; i < 4; i++)
        #pragma unroll
        for (int j = 0; j < NF; j++)
            #pragma unroll
            for (int c = 0; c < 4; c++) acc[i][j][c] = 0.f;

    // prologue: stages 0..NSTG-2
    #pragma unroll
    for (int s = 0; s < NSTG - 1; s++) {
        if (s < nt) load_tiles(s, s * BK);
        cpa_commit();
    }

    int st = 0;
    for (int it = 0; it < nt; it++) {
        cpa_wait<NSTG - 2>();
        __syncthreads();

        int pf = it + NSTG - 1;
        if (pf < nt) load_tiles(pf % NSTG, pf * BK);
        cpa_commit();

        const float* Ab = sm + st * ST;
        const float* Bb = sm + st * ST + ASZ;

        #pragma unroll
        for (int ks = 0; ks < BK; ks += 8) {
            uint32_t afr[4][4];
            #pragma unroll
            for (int mi = 0; mi < 4; mi++) {
                const float* ap = Ab + (warp_m * 64 + mi * 16 + g) * (BK + 4) + ks + tg;
                afr[mi][0] = __float_as_uint(ap[0]);
                afr[mi][1] = __float_as_uint(ap[8 * (BK + 4)]);
                afr[mi][2] = __float_as_uint(ap[4]);
                afr[mi][3] = __float_as_uint(ap[8 * (BK + 4) + 4]);
            }
            uint32_t bfr[NF][2];
            #pragma unroll
            for (int ni = 0; ni < NF; ni++) {
                if (TB) {
                    const float* bp = Bb + (warp_n * WN + ni * 8 + g) * (BK + 4) + ks + tg;
                    bfr[ni][0] = __float_as_uint(bp[0]);
                    bfr[ni][1] = __float_as_uint(bp[4]);
                } else {
                    const float* bp = Bb + (ks + tg) * (BN + 8) + warp_n * WN + ni * 8 + g;
                    bfr[ni][0] = __float_as_uint(bp[0]);
                    bfr[ni][1] = __float_as_uint(bp[4 * (BN + 8)]);
                }
            }
            #pragma unroll
            for (int mi = 0; mi < 4; mi++)
                #pragma unroll
                for (int ni = 0; ni < NF; ni++)
                    mma_tf32(acc[mi][ni], afr[mi], bfr[ni]);
        }
        st++; if (st == NSTG) st = 0;
    }

    // epilogue
    #pragma unroll
    for (int mi = 0; mi < 4; mi++) {
        #pragma unroll
        for (int ni = 0; ni < NF; ni++) {
            int r0 = m0 + warp_m * 64 + mi * 16 + g;
            int c0 = n0 + warp_n * WN + ni * 8 + 2 * tg;
            #pragma unroll
            for (int cc = 0; cc < 4; cc++) {
                int m = r0 + (cc >> 1) * 8;
                int n = c0 + (cc & 1);
                float v = acc[mi][ni][cc] * alpha;
                long long ci = (long long)m * ldc + n;
                if (epi == 1) {
                    v += bias[n];
                    v = 0.5f * v * (1.0f + erff(v * 0.70710678118654752f));
                } else if (epi == 2) {
                    v += bias[n] + C[ci];
                } else if (epi == 3) {
                    v += C[ci];
                }
                if (rnd) v = tf32r(v);
                C[ci] = v;
            }
        }
    }
}

// ---------------------------------------------------------------------------
// Host-side launch helper
// ---------------------------------------------------------------------------
static inline void gemm(const float* A, const float* B, const float* bias, float* C,
                        int M, int N, int K, int lda, int ldb, int ldc, bool tb,
                        int batch, int nh,
                        long long sAo, long long sAi, long long sBo, long long sBi,
                        long long sCo, long long sCi,
                        int epi, float alpha, int causal, int trik, int rnd)
{
    dim3 block(256);
    if (N % 128 == 0) {
        constexpr int ASZ = BM * (BK + 4);
        dim3 grid(N / 128, M / BM, batch);
        if (tb) {
            size_t bytes = (size_t)NSTG * (ASZ + 128 * (BK + 4)) * 4;
            gemm_tc<128, true><<<grid, block, bytes>>>(A, B, bias, C, M, N, K, lda, ldb, ldc,
                nh, sAo, sAi, sBo, sBi, sCo, sCi, epi, alpha, causal, trik, rnd);
        } else {
            size_t bytes = (size_t)NSTG * (ASZ + BK * (128 + 8)) * 4;
            gemm_tc<128, false><<<grid, block, bytes>>>(A, B, bias, C, M, N, K, lda, ldb, ldc,
                nh, sAo, sAi, sBo, sBi, sCo, sCi, epi, alpha, causal, trik, rnd);
        }
    } else {
        constexpr int ASZ = BM * (BK + 4);
        dim3 grid(N / 64, M / BM, batch);
        if (tb) {
            size_t bytes = (size_t)NSTG * (ASZ + 64 * (BK + 4)) * 4;
            gemm_tc<64, true><<<grid, block, bytes>>>(A, B, bias, C, M, N, K, lda, ldb, ldc,
                nh, sAo, sAi, sBo, sBi, sCo, sCi, epi, alpha, causal, trik, rnd);
        } else {
            size_t bytes = (size_t)NSTG * (ASZ + BK * (64 + 8)) * 4;
            gemm_tc<64, false><<<grid, block, bytes>>>(A, B, bias, C, M, N, K, lda, ldb, ldc,
                nh, sAo, sAi, sBo, sBi, sCo, sCi, epi, alpha, causal, trik, rnd);
        }
    }
}

extern "C" void kernel_launch(void* const* d_in, const int* in_sizes, int n_in,
                              void* d_out, int out_size)
{
    (void)in_sizes; (void)n_in; (void)out_size;
    const int*   idx  = (const int*)  d_in[0];
    const float* wte  = (const float*)d_in[1];
    const float* wpe  = (const float*)d_in[2];
    const float* Wq   = (const float*)d_in[3];
    const float* Wk   = (const float*)d_in[4];
    const float* Wv   = (const float*)d_in[5];
    const float* Wo   = (const float*)d_in[6];
    const float* ln1g = (const float*)d_in[7];
    const float* ln1b = (const float*)d_in[8];
    const float* ln2g = (const float*)d_in[9];
    const float* ln2b = (const float*)d_in[10];
    const float* W1   = (const float*)d_in[11];
    const float* b1   = (const float*)d_in[12];
    const float* W2   = (const float*)d_in[13];
    const float* b2   = (const float*)d_in[14];
    const float* lnfg = (const float*)d_in[15];
    const float* lnfb = (const float*)d_in[16];
    float* out = (float*)d_out;

    float *x, *h, *q, *k, *v, *o, *f, *s;
    float *wq, *wk, *wv, *wo, *w1, *w2, *wt;
    cudaGetSymbolAddress((void**)&x, g_x);
    cudaGetSymbolAddress((void**)&h, g_h);
    cudaGetSymbolAddress((void**)&q, g_q);
    cudaGetSymbolAddress((void**)&k, g_k);
    cudaGetSymbolAddress((void**)&v, g_v);
    cudaGetSymbolAddress((void**)&o, g_o);
    cudaGetSymbolAddress((void**)&f, g_f);
    cudaGetSymbolAddress((void**)&s, g_s);
    cudaGetSymbolAddress((void**)&wq, g_wq);
    cudaGetSymbolAddress((void**)&wk, g_wk);
    cudaGetSymbolAddress((void**)&wv, g_wv);
    cudaGetSymbolAddress((void**)&wo, g_wo);
    cudaGetSymbolAddress((void**)&w1, g_w1);
    cudaGetSymbolAddress((void**)&w2, g_w2);
    cudaGetSymbolAddress((void**)&wt, g_wte);

    // raise dynamic smem limits (idempotent; max needed 61440B)
    cudaFuncSetAttribute(gemm_tc<128, true >, cudaFuncAttributeMaxDynamicSharedMemorySize, 64 * 1024);
    cudaFuncSetAttribute(gemm_tc<128, false>, cudaFuncAttributeMaxDynamicSharedMemorySize, 64 * 1024);
    cudaFuncSetAttribute(gemm_tc<64,  true >, cudaFuncAttributeMaxDynamicSharedMemorySize, 64 * 1024);
    cudaFuncSetAttribute(gemm_tc<64,  false>, cudaFuncAttributeMaxDynamicSharedMemorySize, 64 * 1024);

    // pre-round weights to tf32
    {
        long long nqk = (long long)LL * EE * EE / 4;
        round_copy<<<(unsigned)((nqk + 255) / 256), 256>>>(Wq, wq, nqk);
        round_copy<<<(unsigned)((nqk + 255) / 256), 256>>>(Wk, wk, nqk);
        round_copy<<<(unsigned)((nqk + 255) / 256), 256>>>(Wv, wv, nqk);
        round_copy<<<(unsigned)((nqk + 255) / 256), 256>>>(Wo, wo, nqk);
        long long nff = (long long)LL * EE * FF / 4;
        round_copy<<<(unsigned)((nff + 255) / 256), 256>>>(W1, w1, nff);
        round_copy<<<(unsigned)((nff + 255) / 256), 256>>>(W2, w2, nff);
        long long nte = (long long)VV * EE / 4;
        round_copy<<<(unsigned)((nte + 255) / 256), 256>>>(wte, wt, nte);
    }

    embed_kernel<<<(MM * EE) / 256, 256>>>(idx, wte, wpe, x);

    const long long EE2 = (long long)EE * EE;
    const long long TE  = (long long)TT * EE;
    const long long T2  = (long long)TT * TT;

    for (int l = 0; l < LL; l++) {
        ln_kernel<<<MM, 256>>>(x, ln1g + (long long)l * EE, ln1b + (long long)l * EE, h);

        gemm(h, wq + l * EE2, nullptr, q, MM, EE, EE, EE, EE, EE, false,
             1, 1, 0, 0, 0, 0, 0, 0, 0, 1.0f, 0, 0, 1);
        gemm(h, wk + l * EE2, nullptr, k, MM, EE, EE, EE, EE, EE, false,
             1, 1, 0, 0, 0, 0, 0, 0, 0, 1.0f, 0, 0, 1);
        gemm(h, wv + l * EE2, nullptr, v, MM, EE, EE, EE, EE, EE, false,
             1, 1, 0, 0, 0, 0, 0, 0, 0, 1.0f, 0, 0, 1);

        // scores: S = Q @ K^T / 8, causal block skip (raw fp32 out for softmax)
        gemm(q, k, nullptr, s, TT, TT, DD, EE, EE, TT, true,
             BB * HH, HH,
             TE, DD, TE, DD, (long long)HH * T2, T2,
             0, 0.125f, 1, 0, 0);

        { dim3 g2(TT, BB * HH); softmax_kernel<<<g2, 256>>>(s); }

        // O = P @ V ; P is lower-triangular -> trim K to m0+BM
        gemm(s, v, nullptr, o, TT, DD, TT, TT, EE, EE, false,
             BB * HH, HH,
             (long long)HH * T2, T2, TE, DD, TE, DD,
             0, 1.0f, 0, 1, 1);

        gemm(o, wo + l * EE2, nullptr, x, MM, EE, EE, EE, EE, EE, false,
             1, 1, 0, 0, 0, 0, 0, 0, 3, 1.0f, 0, 0, 0);

        ln_kernel<<<MM, 256>>>(x, ln2g + (long long)l * EE, ln2b + (long long)l * EE, h);

        gemm(h, w1 + (long long)l * EE * FF, b1 + (long long)l * FF, f,
             MM, FF, EE, EE, FF, FF, false,
             1, 1, 0, 0, 0, 0, 0, 0, 1, 1.0f, 0, 0, 1);

        gemm(f, w2 + (long long)l * FF * EE, b2 + (long long)l * EE, x,
             MM, EE, FF, FF, EE, EE, false,
             1, 1, 0, 0, 0, 0, 0, 0, 2, 1.0f, 0, 0, 0);
    }

    ln_kernel<<<MM, 256>>>(x, lnfg, lnfb, h);

    gemm(h, wt, nullptr, out, MM, VV, EE, EE, EE, VV, true,
         1, 1, 0, 0, 0, 0, 0, 0, 0, 1.0f, 0, 0, 0);
}

// round 7
// speedup vs baseline: 3.8566x; 1.1562x over previous
#include <cuda_runtime.h>
#include <cuda_bf16.h>
#include <math.h>
#include <stdint.h>

// Problem constants
#define BB 4
#define TT 1024
#define EE 1024
#define HH 16
#define DD 64
#define FF 4096
#define LL 6
#define VV 32000
#define MM (BB*TT)
#define LN_EPS 1e-5f

// ---------------------------------------------------------------------------
// Scratch (device globals; no cudaMalloc allowed)
// ---------------------------------------------------------------------------
__device__ float g_x[(size_t)MM * EE];
__device__ float g_h[(size_t)MM * EE];
__device__ float g_q[(size_t)MM * EE];
__device__ float g_k[(size_t)MM * EE];
__device__ float g_v[(size_t)MM * EE];
__device__ float g_o[(size_t)MM * EE];
__device__ float g_f[(size_t)MM * FF];
// pre-rounded (tf32-in-fp32) weights
__device__ float g_wq[(size_t)LL * EE * EE];
__device__ float g_wk[(size_t)LL * EE * EE];
__device__ float g_wv[(size_t)LL * EE * EE];
__device__ float g_wo[(size_t)LL * EE * EE];
__device__ float g_w1[(size_t)LL * EE * FF];
__device__ float g_w2[(size_t)LL * FF * EE];
__device__ float g_wte[(size_t)VV * EE];

__device__ __forceinline__ float tf32r(float x) {
    uint32_t u;
    asm("cvt.rna.tf32.f32 %0, %1;" : "=r"(u) : "f"(x));
    return __uint_as_float(u);
}

// ---------------------------------------------------------------------------
// Round-copy: out[i] = tf32(in[i])
// ---------------------------------------------------------------------------
__global__ __launch_bounds__(256) void round_copy(const float* __restrict__ in,
                                                  float* __restrict__ out, long long n4)
{
    long long i = (long long)blockIdx.x * 256 + threadIdx.x;
    if (i < n4) {
        float4 v = ((const float4*)in)[i];
        v.x = tf32r(v.x); v.y = tf32r(v.y); v.z = tf32r(v.z); v.w = tf32r(v.w);
        ((float4*)out)[i] = v;
    }
}

// ---------------------------------------------------------------------------
// Embedding
// ---------------------------------------------------------------------------
__global__ void embed_kernel(const int* __restrict__ idx,
                             const float* __restrict__ wte,
                             const float* __restrict__ wpe,
                             float* __restrict__ x)
{
    long long i = (long long)blockIdx.x * blockDim.x + threadIdx.x;
    int bt = (int)(i >> 10);
    int e  = (int)(i & 1023);
    int t  = bt & (TT - 1);
    x[i] = wte[(long long)idx[bt] * EE + e] + wpe[(long long)t * EE + e];
}

// ---------------------------------------------------------------------------
// LayerNorm (output tf32-rounded; only feeds GEMMs)
// ---------------------------------------------------------------------------
__device__ __forceinline__ float warp_sum(float v) {
    #pragma unroll
    for (int o = 16; o > 0; o >>= 1) v += __shfl_xor_sync(0xffffffffu, v, o);
    return v;
}

__global__ __launch_bounds__(256) void ln_kernel(const float* __restrict__ x,
                                                 const float* __restrict__ gamma,
                                                 const float* __restrict__ beta,
                                                 float* __restrict__ out)
{
    int row = blockIdx.x;
    const float* xr = x + (long long)row * EE;
    float* orow = out + (long long)row * EE;
    int tid = threadIdx.x;

    float s = 0.f, s2 = 0.f;
    float vals[4];
    #pragma unroll
    for (int u = 0; u < 4; u++) {
        float v = xr[tid + u * 256];
        vals[u] = v;
        s += v; s2 += v * v;
    }
    s  = warp_sum(s);
    s2 = warp_sum(s2);
    __shared__ float shs[8], shs2[8];
    int wid = tid >> 5, lane = tid & 31;
    if (lane == 0) { shs[wid] = s; shs2[wid] = s2; }
    __syncthreads();
    float ts = 0.f, ts2 = 0.f;
    #pragma unroll
    for (int i = 0; i < 8; i++) { ts += shs[i]; ts2 += shs2[i]; }
    float mean = ts * (1.0f / EE);
    float var  = ts2 * (1.0f / EE) - mean * mean;
    float rstd = rsqrtf(var + LN_EPS);
    #pragma unroll
    for (int u = 0; u < 4; u++) {
        int j = tid + u * 256;
        orow[j] = tf32r((vals[u] - mean) * rstd * gamma[j] + beta[j]);
    }
}

// ---------------------------------------------------------------------------
// cp.async helpers
// ---------------------------------------------------------------------------
__device__ __forceinline__ void cpa16(uint32_t dst, const float* src) {
    asm volatile("cp.async.cg.shared.global [%0], [%1], 16;" :: "r"(dst), "l"(src));
}
__device__ __forceinline__ void cpa_commit() {
    asm volatile("cp.async.commit_group;");
}
template<int N>
__device__ __forceinline__ void cpa_wait() {
    asm volatile("cp.async.wait_group %0;" :: "n"(N));
}

__device__ __forceinline__ void mma_tf32(float* c, const uint32_t* a, const uint32_t* b) {
    asm volatile(
        "mma.sync.aligned.m16n8k8.row.col.f32.tf32.tf32.f32 "
        "{%0,%1,%2,%3}, {%4,%5,%6,%7}, {%8,%9}, {%0,%1,%2,%3};\n"
        : "+f"(c[0]), "+f"(c[1]), "+f"(c[2]), "+f"(c[3])
        : "r"(a[0]), "r"(a[1]), "r"(a[2]), "r"(a[3]), "r"(b[0]), "r"(b[1]));
}

// ---------------------------------------------------------------------------
// Fused flash attention (causal), tf32 tensor cores.
// CTA: 128 q-rows of one (b,h). 8 warps x 16 rows. D=64.
// smem: [ K0(128x68) V0(128x72) | K1 V1 | Ps(128x132) ]  (floats)
// Pipeline per j-block: wait(stage ready) -> syncthreads (all warps done with
// the stage we're about to overwrite) -> prefetch next stage -> compute.
// ---------------------------------------------------------------------------
#define KST 68
#define VST 72
#define PST 132
#define KVSTAGE (128*KST + 128*VST)          // 17920 floats
#define PS_OFF  (2*KVSTAGE)                  // 35840
#define FA_SMEM ((PS_OFF + 128*PST) * 4)     // 210944 bytes

__global__ __launch_bounds__(256, 1) void flash_kernel(
    const float* __restrict__ Q, const float* __restrict__ K,
    const float* __restrict__ V, float* __restrict__ O)
{
    extern __shared__ float sm[];

    int mb = blockIdx.x;
    int bh = blockIdx.y;
    int b = bh >> 4, h = bh & 15;
    int m0 = mb * 128;

    const float* Qp = Q + (long long)b * TT * EE + (long long)h * DD;
    const float* Kp = K + (long long)b * TT * EE + (long long)h * DD;
    const float* Vp = V + (long long)b * TT * EE + (long long)h * DD;
    float*       Op = O + (long long)b * TT * EE + (long long)h * DD;

    int tid = threadIdx.x, warp = tid >> 5, lane = tid & 31;
    int g = lane >> 2, tg = lane & 3;

    uint32_t smem_u32 = (uint32_t)__cvta_generic_to_shared(sm);

    auto load_kv = [&](int stage, int j0) {
        uint32_t base = smem_u32 + (uint32_t)(stage * KVSTAGE) * 4u;
        #pragma unroll
        for (int i = 0; i < 8; i++) {
            int idx = tid + i * 256;
            int row = idx >> 4;
            int col = (idx & 15) << 2;
            cpa16(base + (uint32_t)(row * KST + col) * 4u,
                  Kp + (long long)(j0 + row) * EE + col);
        }
        #pragma unroll
        for (int i = 0; i < 8; i++) {
            int idx = tid + i * 256;
            int row = idx >> 4;
            int col = (idx & 15) << 2;
            cpa16(base + (uint32_t)(128 * KST + row * VST + col) * 4u,
                  Vp + (long long)(j0 + row) * EE + col);
        }
    };

    // stage Q into Ps region (stride KST), load KV block 0
    {
        uint32_t qbase = smem_u32 + (uint32_t)PS_OFF * 4u;
        #pragma unroll
        for (int i = 0; i < 8; i++) {
            int idx = tid + i * 256;
            int row = idx >> 4;
            int col = (idx & 15) << 2;
            cpa16(qbase + (uint32_t)(row * KST + col) * 4u,
                  Qp + (long long)(m0 + row) * EE + col);
        }
        cpa_commit();
        load_kv(0, 0);
        cpa_commit();
        cpa_wait<0>();
        __syncthreads();
    }

    // Q fragments (scaled by 1/8 — exact power of 2, stays tf32)
    uint32_t qf[8][4];
    {
        const float* Qs = sm + PS_OFF;
        #pragma unroll
        for (int kc = 0; kc < 8; kc++) {
            const float* qp2 = Qs + (warp * 16 + g) * KST + kc * 8 + tg;
            qf[kc][0] = __float_as_uint(0.125f * qp2[0]);
            qf[kc][1] = __float_as_uint(0.125f * qp2[8 * KST]);
            qf[kc][2] = __float_as_uint(0.125f * qp2[4]);
            qf[kc][3] = __float_as_uint(0.125f * qp2[8 * KST + 4]);
        }
    }
    __syncthreads();  // Ps region now free for P tiles

    float m_[2] = {-1e30f, -1e30f};
    float l_[2] = {0.f, 0.f};
    float oacc[8][4];
    #pragma unroll
    for (int i = 0; i < 8; i++)
        #pragma unroll
        for (int c = 0; c < 4; c++) oacc[i][c] = 0.f;

    int nblk = mb;  // diagonal block index
    for (int jb = 0; jb <= nblk; jb++) {
        // stage jb&1 loads complete...
        cpa_wait<0>();
        // ...and ALL warps are done reading the stage we prefetch into below
        __syncthreads();
        if (jb < nblk) {
            load_kv((jb + 1) & 1, (jb + 1) * 128);
            cpa_commit();
        }

        const float* Ks = sm + (jb & 1) * KVSTAGE;
        const float* Vs = Ks + 128 * KST;

        // ---- S = Q @ K^T : warp computes 16 x 128 ----
        float sacc[16][4];
        #pragma unroll
        for (int nf = 0; nf < 16; nf++)
            #pragma unroll
            for (int c = 0; c < 4; c++) sacc[nf][c] = 0.f;

        #pragma unroll
        for (int kc = 0; kc < 8; kc++) {
            #pragma unroll
            for (int nf = 0; nf < 16; nf++) {
                const float* bp = Ks + (nf * 8 + g) * KST + kc * 8 + tg;
                uint32_t bfr[2];
                bfr[0] = __float_as_uint(bp[0]);
                bfr[1] = __float_as_uint(bp[4]);
                mma_tf32(sacc[nf], qf[kc], bfr);
            }
        }

        // ---- causal mask on diagonal block ----
        if (jb == nblk) {
            int i0 = m0 + warp * 16 + g;
            #pragma unroll
            for (int nf = 0; nf < 16; nf++) {
                int j0c = jb * 128 + nf * 8 + 2 * tg;
                if (j0c     > i0)     sacc[nf][0] = -1e30f;
                if (j0c + 1 > i0)     sacc[nf][1] = -1e30f;
                if (j0c     > i0 + 8) sacc[nf][2] = -1e30f;
                if (j0c + 1 > i0 + 8) sacc[nf][3] = -1e30f;
            }
        }

        // ---- online softmax ----
        float rm0 = -1e30f, rm1 = -1e30f;
        #pragma unroll
        for (int nf = 0; nf < 16; nf++) {
            rm0 = fmaxf(rm0, fmaxf(sacc[nf][0], sacc[nf][1]));
            rm1 = fmaxf(rm1, fmaxf(sacc[nf][2], sacc[nf][3]));
        }
        rm0 = fmaxf(rm0, __shfl_xor_sync(0xffffffffu, rm0, 1));
        rm0 = fmaxf(rm0, __shfl_xor_sync(0xffffffffu, rm0, 2));
        rm1 = fmaxf(rm1, __shfl_xor_sync(0xffffffffu, rm1, 1));
        rm1 = fmaxf(rm1, __shfl_xor_sync(0xffffffffu, rm1, 2));

        float mn0 = fmaxf(m_[0], rm0), mn1 = fmaxf(m_[1], rm1);
        float sc0 = __expf(m_[0] - mn0), sc1 = __expf(m_[1] - mn1);
        m_[0] = mn0; m_[1] = mn1;

        float rs0 = 0.f, rs1 = 0.f;
        #pragma unroll
        for (int nf = 0; nf < 16; nf++) {
            sacc[nf][0] = __expf(sacc[nf][0] - mn0);
            sacc[nf][1] = __expf(sacc[nf][1] - mn0);
            sacc[nf][2] = __expf(sacc[nf][2] - mn1);
            sacc[nf][3] = __expf(sacc[nf][3] - mn1);
            rs0 += sacc[nf][0] + sacc[nf][1];
            rs1 += sacc[nf][2] + sacc[nf][3];
        }
        rs0 += __shfl_xor_sync(0xffffffffu, rs0, 1);
        rs0 += __shfl_xor_sync(0xffffffffu, rs0, 2);
        rs1 += __shfl_xor_sync(0xffffffffu, rs1, 1);
        rs1 += __shfl_xor_sync(0xffffffffu, rs1, 2);
        l_[0] = l_[0] * sc0 + rs0;
        l_[1] = l_[1] * sc1 + rs1;

        #pragma unroll
        for (int nf = 0; nf < 8; nf++) {
            oacc[nf][0] *= sc0; oacc[nf][1] *= sc0;
            oacc[nf][2] *= sc1; oacc[nf][3] *= sc1;
        }

        // ---- P -> smem (tf32, own 16-row band only) ----
        {
            float* Pw = sm + PS_OFF + (warp * 16 + g) * PST;
            #pragma unroll
            for (int nf = 0; nf < 16; nf++) {
                int c = nf * 8 + 2 * tg;
                float2 p0 = make_float2(tf32r(sacc[nf][0]), tf32r(sacc[nf][1]));
                float2 p1 = make_float2(tf32r(sacc[nf][2]), tf32r(sacc[nf][3]));
                *(float2*)(Pw + c)           = p0;
                *(float2*)(Pw + 8 * PST + c) = p1;
            }
        }
        __syncwarp();

        // ---- O += P @ V : 16 x 64, k = 128 ----
        const float* Pr = sm + PS_OFF + (warp * 16 + g) * PST;
        #pragma unroll
        for (int kc = 0; kc < 16; kc++) {
            uint32_t afr[4];
            const float* ap = Pr + kc * 8 + tg;
            afr[0] = __float_as_uint(ap[0]);
            afr[1] = __float_as_uint(ap[8 * PST]);
            afr[2] = __float_as_uint(ap[4]);
            afr[3] = __float_as_uint(ap[8 * PST + 4]);
            #pragma unroll
            for (int nf = 0; nf < 8; nf++) {
                const float* bp = Vs + (kc * 8 + tg) * VST + nf * 8 + g;
                uint32_t bfr[2];
                bfr[0] = __float_as_uint(bp[0]);
                bfr[1] = __float_as_uint(bp[4 * VST]);
                mma_tf32(oacc[nf], afr, bfr);
            }
        }
    }

    // ---- epilogue: O / l, tf32-rounded (feeds Wo GEMM) ----
    float inv0 = 1.0f / l_[0], inv1 = 1.0f / l_[1];
    int r0 = m0 + warp * 16 + g;
    #pragma unroll
    for (int nf = 0; nf < 8; nf++) {
        int c = nf * 8 + 2 * tg;
        float* o0 = Op + (long long)r0 * EE + c;
        float* o1 = Op + (long long)(r0 + 8) * EE + c;
        o0[0] = tf32r(oacc[nf][0] * inv0);
        o0[1] = tf32r(oacc[nf][1] * inv0);
        o1[0] = tf32r(oacc[nf][2] * inv1);
        o1[1] = tf32r(oacc[nf][3] * inv1);
    }
}

// ---------------------------------------------------------------------------
// Tensor-core tf32 GEMM, 3-stage cp.async pipeline (unchanged from R5)
// ---------------------------------------------------------------------------
#define BM 128
#define BK 16
#define NSTG 3

template<int BN, bool TB>
__global__ __launch_bounds__(256) void gemm_tc(
    const float* __restrict__ A, const float* __restrict__ Bm,
    const float* __restrict__ bias, float* __restrict__ C,
    int M, int N, int K, int lda, int ldb, int ldc,
    int nh,
    long long sAo, long long sAi, long long sBo, long long sBi,
    long long sCo, long long sCi,
    int epi, float alpha, int causal, int trik, int rnd)
{
    constexpr int ASZ = BM * (BK + 4);
    constexpr int BSZ = TB ? BN * (BK + 4) : BK * (BN + 8);
    constexpr int ST  = ASZ + BSZ;

    extern __shared__ float sm[];

    int z = blockIdx.z;
    A  += (long long)(z / nh) * sAo + (long long)(z % nh) * sAi;
    Bm += (long long)(z / nh) * sBo + (long long)(z % nh) * sBi;
    C  += (long long)(z / nh) * sCo + (long long)(z % nh) * sCi;

    int n0 = blockIdx.x * BN;
    int m0 = blockIdx.y * BM;
    if (causal && n0 > m0 + BM - 1) return;

    int K_eff = trik ? min(K, m0 + BM) : K;
    int nt = K_eff / BK;

    int tid  = threadIdx.x;
    int warp = tid >> 5, lane = tid & 31;
    int g  = lane >> 2;
    int tg = lane & 3;
    int warp_m = warp >> 2;
    int warp_n = warp & 3;
    constexpr int NF = BN / 32;
    constexpr int WN = BN / 4;

    uint32_t smem_u32 = (uint32_t)__cvta_generic_to_shared(sm);

    auto load_tiles = [&](int st, int k0) {
        uint32_t sb = smem_u32 + (uint32_t)(st * ST) * 4u;
        #pragma unroll
        for (int i = 0; i < 2; i++) {
            int idx = tid + i * 256;
            int row = idx >> 2;
            int kc  = (idx & 3) << 2;
            cpa16(sb + (uint32_t)(row * (BK + 4) + kc) * 4u,
                  A + (long long)(m0 + row) * lda + k0 + kc);
        }
        if (!TB) {
            constexpr int CH = (BK * BN / 4) / 256;
            #pragma unroll
            for (int i = 0; i < CH; i++) {
                int idx = tid + i * 256;
                int row = idx / (BN / 4);
                int nc  = (idx % (BN / 4)) << 2;
                cpa16(sb + (uint32_t)(ASZ + row * (BN + 8) + nc) * 4u,
                      Bm + (long long)(k0 + row) * ldb + n0 + nc);
            }
        } else {
            constexpr int CH = (BN * BK / 4) / 256;
            #pragma unroll
            for (int i = 0; i < CH; i++) {
                int idx = tid + i * 256;
                int row = idx >> 2;
                int kc  = (idx & 3) << 2;
                cpa16(sb + (uint32_t)(ASZ + row * (BK + 4) + kc) * 4u,
                      Bm + (long long)(n0 + row) * ldb + k0 + kc);
            }
        }
    };

    float acc[4][NF][4];
    #pragma unroll
    for (int i = 0; i < 4; i++)
        #pragma unroll
        for (int j = 0; j < NF; j++)
            #pragma unroll
            for (int c = 0; c < 4; c++) acc[i][j][c] = 0.f;

    #pragma unroll
    for (int s = 0; s < NSTG - 1; s++) {
        if (s < nt) load_tiles(s, s * BK);
        cpa_commit();
    }

    int st = 0;
    for (int it = 0; it < nt; it++) {
        cpa_wait<NSTG - 2>();
        __syncthreads();

        int pf = it + NSTG - 1;
        if (pf < nt) load_tiles(pf % NSTG, pf * BK);
        cpa_commit();

        const float* Ab = sm + st * ST;
        const float* Bb = sm + st * ST + ASZ;

        #pragma unroll
        for (int ks = 0; ks < BK; ks += 8) {
            uint32_t afr[4][4];
            #pragma unroll
            for (int mi = 0; mi < 4; mi++) {
                const float* ap = Ab + (warp_m * 64 + mi * 16 + g) * (BK + 4) + ks + tg;
                afr[mi][0] = __float_as_uint(ap[0]);
                afr[mi][1] = __float_as_uint(ap[8 * (BK + 4)]);
                afr[mi][2] = __float_as_uint(ap[4]);
                afr[mi][3] = __float_as_uint(ap[8 * (BK + 4) + 4]);
            }
            uint32_t bfr[NF][2];
            #pragma unroll
            for (int ni = 0; ni < NF; ni++) {
                if (TB) {
                    const float* bp = Bb + (warp_n * WN + ni * 8 + g) * (BK + 4) + ks + tg;
                    bfr[ni][0] = __float_as_uint(bp[0]);
                    bfr[ni][1] = __float_as_uint(bp[4]);
                } else {
                    const float* bp = Bb + (ks + tg) * (BN + 8) + warp_n * WN + ni * 8 + g;
                    bfr[ni][0] = __float_as_uint(bp[0]);
                    bfr[ni][1] = __float_as_uint(bp[4 * (BN + 8)]);
                }
            }
            #pragma unroll
            for (int mi = 0; mi < 4; mi++)
                #pragma unroll
                for (int ni = 0; ni < NF; ni++)
                    mma_tf32(acc[mi][ni], afr[mi], bfr[ni]);
        }
        st++; if (st == NSTG) st = 0;
    }

    #pragma unroll
    for (int mi = 0; mi < 4; mi++) {
        #pragma unroll
        for (int ni = 0; ni < NF; ni++) {
            int r0 = m0 + warp_m * 64 + mi * 16 + g;
            int c0 = n0 + warp_n * WN + ni * 8 + 2 * tg;
            #pragma unroll
            for (int cc = 0; cc < 4; cc++) {
                int m = r0 + (cc >> 1) * 8;
                int n = c0 + (cc & 1);
                float v = acc[mi][ni][cc] * alpha;
                long long ci = (long long)m * ldc + n;
                if (epi == 1) {
                    v += bias[n];
                    v = 0.5f * v * (1.0f + erff(v * 0.70710678118654752f));
                } else if (epi == 2) {
                    v += bias[n] + C[ci];
                } else if (epi == 3) {
                    v += C[ci];
                }
                if (rnd) v = tf32r(v);
                C[ci] = v;
            }
        }
    }
}

// ---------------------------------------------------------------------------
// Host-side launch helper
// ---------------------------------------------------------------------------
static inline void gemm(const float* A, const float* B, const float* bias, float* C,
                        int M, int N, int K, int lda, int ldb, int ldc, bool tb,
                        int batch, int nh,
                        long long sAo, long long sAi, long long sBo, long long sBi,
                        long long sCo, long long sCi,
                        int epi, float alpha, int causal, int trik, int rnd)
{
    dim3 block(256);
    constexpr int ASZ = BM * (BK + 4);
    if (N % 128 == 0) {
        dim3 grid(N / 128, M / BM, batch);
        if (tb) {
            size_t bytes = (size_t)NSTG * (ASZ + 128 * (BK + 4)) * 4;
            gemm_tc<128, true><<<grid, block, bytes>>>(A, B, bias, C, M, N, K, lda, ldb, ldc,
                nh, sAo, sAi, sBo, sBi, sCo, sCi, epi, alpha, causal, trik, rnd);
        } else {
            size_t bytes = (size_t)NSTG * (ASZ + BK * (128 + 8)) * 4;
            gemm_tc<128, false><<<grid, block, bytes>>>(A, B, bias, C, M, N, K, lda, ldb, ldc,
                nh, sAo, sAi, sBo, sBi, sCo, sCi, epi, alpha, causal, trik, rnd);
        }
    } else {
        dim3 grid(N / 64, M / BM, batch);
        if (tb) {
            size_t bytes = (size_t)NSTG * (ASZ + 64 * (BK + 4)) * 4;
            gemm_tc<64, true><<<grid, block, bytes>>>(A, B, bias, C, M, N, K, lda, ldb, ldc,
                nh, sAo, sAi, sBo, sBi, sCo, sCi, epi, alpha, causal, trik, rnd);
        } else {
            size_t bytes = (size_t)NSTG * (ASZ + BK * (64 + 8)) * 4;
            gemm_tc<64, false><<<grid, block, bytes>>>(A, B, bias, C, M, N, K, lda, ldb, ldc,
                nh, sAo, sAi, sBo, sBi, sCo, sCi, epi, alpha, causal, trik, rnd);
        }
    }
}

extern "C" void kernel_launch(void* const* d_in, const int* in_sizes, int n_in,
                              void* d_out, int out_size)
{
    (void)in_sizes; (void)n_in; (void)out_size;
    const int*   idx  = (const int*)  d_in[0];
    const float* wte  = (const float*)d_in[1];
    const float* wpe  = (const float*)d_in[2];
    const float* Wq   = (const float*)d_in[3];
    const float* Wk   = (const float*)d_in[4];
    const float* Wv   = (const float*)d_in[5];
    const float* Wo   = (const float*)d_in[6];
    const float* ln1g = (const float*)d_in[7];
    const float* ln1b = (const float*)d_in[8];
    const float* ln2g = (const float*)d_in[9];
    const float* ln2b = (const float*)d_in[10];
    const float* W1   = (const float*)d_in[11];
    const float* b1   = (const float*)d_in[12];
    const float* W2   = (const float*)d_in[13];
    const float* b2   = (const float*)d_in[14];
    const float* lnfg = (const float*)d_in[15];
    const float* lnfb = (const float*)d_in[16];
    float* out = (float*)d_out;

    float *x, *h, *q, *k, *v, *o, *f;
    float *wq, *wk, *wv, *wo, *w1, *w2, *wt;
    cudaGetSymbolAddress((void**)&x, g_x);
    cudaGetSymbolAddress((void**)&h, g_h);
    cudaGetSymbolAddress((void**)&q, g_q);
    cudaGetSymbolAddress((void**)&k, g_k);
    cudaGetSymbolAddress((void**)&v, g_v);
    cudaGetSymbolAddress((void**)&o, g_o);
    cudaGetSymbolAddress((void**)&f, g_f);
    cudaGetSymbolAddress((void**)&wq, g_wq);
    cudaGetSymbolAddress((void**)&wk, g_wk);
    cudaGetSymbolAddress((void**)&wv, g_wv);
    cudaGetSymbolAddress((void**)&wo, g_wo);
    cudaGetSymbolAddress((void**)&w1, g_w1);
    cudaGetSymbolAddress((void**)&w2, g_w2);
    cudaGetSymbolAddress((void**)&wt, g_wte);

    cudaFuncSetAttribute(gemm_tc<128, true >, cudaFuncAttributeMaxDynamicSharedMemorySize, 64 * 1024);
    cudaFuncSetAttribute(gemm_tc<128, false>, cudaFuncAttributeMaxDynamicSharedMemorySize, 64 * 1024);
    cudaFuncSetAttribute(gemm_tc<64,  true >, cudaFuncAttributeMaxDynamicSharedMemorySize, 64 * 1024);
    cudaFuncSetAttribute(gemm_tc<64,  false>, cudaFuncAttributeMaxDynamicSharedMemorySize, 64 * 1024);
    cudaFuncSetAttribute(flash_kernel, cudaFuncAttributeMaxDynamicSharedMemorySize, FA_SMEM);

    // pre-round weights to tf32
    {
        long long nqk = (long long)LL * EE * EE / 4;
        round_copy<<<(unsigned)((nqk + 255) / 256), 256>>>(Wq, wq, nqk);
        round_copy<<<(unsigned)((nqk + 255) / 256), 256>>>(Wk, wk, nqk);
        round_copy<<<(unsigned)((nqk + 255) / 256), 256>>>(Wv, wv, nqk);
        round_copy<<<(unsigned)((nqk + 255) / 256), 256>>>(Wo, wo, nqk);
        long long nff = (long long)LL * EE * FF / 4;
        round_copy<<<(unsigned)((nff + 255) / 256), 256>>>(W1, w1, nff);
        round_copy<<<(unsigned)((nff + 255) / 256), 256>>>(W2, w2, nff);
        long long nte = (long long)VV * EE / 4;
        round_copy<<<(unsigned)((nte + 255) / 256), 256>>>(wte, wt, nte);
    }

    embed_kernel<<<(MM * EE) / 256, 256>>>(idx, wte, wpe, x);

    const long long EE2 = (long long)EE * EE;

    for (int l = 0; l < LL; l++) {
        ln_kernel<<<MM, 256>>>(x, ln1g + (long long)l * EE, ln1b + (long long)l * EE, h);

        gemm(h, wq + l * EE2, nullptr, q, MM, EE, EE, EE, EE, EE, false,
             1, 1, 0, 0, 0, 0, 0, 0, 0, 1.0f, 0, 0, 1);
        gemm(h, wk + l * EE2, nullptr, k, MM, EE, EE, EE, EE, EE, false,
             1, 1, 0, 0, 0, 0, 0, 0, 0, 1.0f, 0, 0, 1);
        gemm(h, wv + l * EE2, nullptr, v, MM, EE, EE, EE, EE, EE, false,
             1, 1, 0, 0, 0, 0, 0, 0, 0, 1.0f, 0, 0, 1);

        // fused causal attention
        {
            dim3 grid(TT / 128, BB * HH);
            flash_kernel<<<grid, 256, FA_SMEM>>>(q, k, v, o);
        }

        gemm(o, wo + l * EE2, nullptr, x, MM, EE, EE, EE, EE, EE, false,
             1, 1, 0, 0, 0, 0, 0, 0, 3, 1.0f, 0, 0, 0);

        ln_kernel<<<MM, 256>>>(x, ln2g + (long long)l * EE, ln2b + (long long)l * EE, h);

        gemm(h, w1 + (long long)l * EE * FF, b1 + (long long)l * FF, f,
             MM, FF, EE, EE, FF, FF, false,
             1, 1, 0, 0, 0, 0, 0, 0, 1, 1.0f, 0, 0, 1);

        gemm(f, w2 + (long long)l * FF * EE, b2 + (long long)l * EE, x,
             MM, EE, FF, FF, EE, EE, false,
             1, 1, 0, 0, 0, 0, 0, 0, 2, 1.0f, 0, 0, 0);
    }

    ln_kernel<<<MM, 256>>>(x, lnfg, lnfb, h);

    gemm(h, wt, nullptr, out, MM, VV, EE, EE, EE, VV, true,
         1, 1, 0, 0, 0, 0, 0, 0, 0, 1.0f, 0, 0, 0);
}

// round 8
// speedup vs baseline: 4.2880x; 1.1119x over previous
#include <cuda_runtime.h>
#include <cuda_bf16.h>
#include <math.h>
#include <stdint.h>

// Problem constants
#define BB 4
#define TT 1024
#define EE 1024
#define HH 16
#define DD 64
#define FF 4096
#define LL 6
#define VV 32000
#define MM (BB*TT)
#define QKVW 3072
#define LN_EPS 1e-5f

// ---------------------------------------------------------------------------
// Scratch (device globals; no cudaMalloc allowed)
// ---------------------------------------------------------------------------
__device__ float g_x[(size_t)MM * EE];
__device__ float g_h[(size_t)MM * EE];
__device__ float g_qkv[(size_t)MM * QKVW];
__device__ float g_o[(size_t)MM * EE];
__device__ float g_f[(size_t)MM * FF];
// pre-rounded (tf32-in-fp32) weights
__device__ float g_wqkv[(size_t)LL * EE * QKVW];
__device__ float g_wo[(size_t)LL * EE * EE];
__device__ float g_w1[(size_t)LL * EE * FF];
__device__ float g_w2[(size_t)LL * FF * EE];
__device__ float g_wte[(size_t)VV * EE];

__device__ __forceinline__ float tf32r(float x) {
    uint32_t u;
    asm("cvt.rna.tf32.f32 %0, %1;" : "=r"(u) : "f"(x));
    return __uint_as_float(u);
}

// Fast exact-grade GELU: A&S 7.1.26 erf, |abs err| <= 1.5e-7
__device__ __forceinline__ float fast_gelu(float v) {
    float x  = v * 0.70710678118654752f;
    float ax = fabsf(x);
    float t  = 1.0f / (1.0f + 0.3275911f * ax);
    float p  = ((((1.061405429f * t - 1.453152027f) * t + 1.421413741f) * t
                 - 0.284496736f) * t + 0.254829592f) * t;
    float er = 1.0f - p * __expf(-x * x);
    er = copysignf(er, x);
    return 0.5f * v * (1.0f + er);
}

// ---------------------------------------------------------------------------
// Round-copy: out[i] = tf32(in[i])
// ---------------------------------------------------------------------------
__global__ __launch_bounds__(256) void round_copy(const float* __restrict__ in,
                                                  float* __restrict__ out, long long n4)
{
    long long i = (long long)blockIdx.x * 256 + threadIdx.x;
    if (i < n4) {
        float4 v = ((const float4*)in)[i];
        v.x = tf32r(v.x); v.y = tf32r(v.y); v.z = tf32r(v.z); v.w = tf32r(v.w);
        ((float4*)out)[i] = v;
    }
}

// Pack Wq|Wk|Wv into [L][E][3E], tf32-rounded.
__global__ __launch_bounds__(256) void pack_qkv(const float* __restrict__ Wq,
                                                const float* __restrict__ Wk,
                                                const float* __restrict__ Wv,
                                                float* __restrict__ out)
{
    long long i = (long long)blockIdx.x * 256 + threadIdx.x;   // float4 index
    const long long row_f4 = QKVW / 4;                          // 768
    long long row  = i / row_f4;                                // l*EE + kk
    int col4 = (int)(i - row * row_f4);
    int sel  = col4 / (EE / 4);
    int c    = col4 - sel * (EE / 4);
    const float* src = (sel == 0 ? Wq : sel == 1 ? Wk : Wv);
    float4 v = ((const float4*)(src + row * EE))[c];
    v.x = tf32r(v.x); v.y = tf32r(v.y); v.z = tf32r(v.z); v.w = tf32r(v.w);
    ((float4*)out)[i] = v;
}

// ---------------------------------------------------------------------------
// Embedding
// ---------------------------------------------------------------------------
__global__ void embed_kernel(const int* __restrict__ idx,
                             const float* __restrict__ wte,
                             const float* __restrict__ wpe,
                             float* __restrict__ x)
{
    long long i = (long long)blockIdx.x * blockDim.x + threadIdx.x;
    int bt = (int)(i >> 10);
    int e  = (int)(i & 1023);
    int t  = bt & (TT - 1);
    x[i] = wte[(long long)idx[bt] * EE + e] + wpe[(long long)t * EE + e];
}

// ---------------------------------------------------------------------------
// LayerNorm (output tf32-rounded; only feeds GEMMs)
// ---------------------------------------------------------------------------
__device__ __forceinline__ float warp_sum(float v) {
    #pragma unroll
    for (int o = 16; o > 0; o >>= 1) v += __shfl_xor_sync(0xffffffffu, v, o);
    return v;
}

__global__ __launch_bounds__(256) void ln_kernel(const float* __restrict__ x,
                                                 const float* __restrict__ gamma,
                                                 const float* __restrict__ beta,
                                                 float* __restrict__ out)
{
    int row = blockIdx.x;
    const float* xr = x + (long long)row * EE;
    float* orow = out + (long long)row * EE;
    int tid = threadIdx.x;

    float s = 0.f, s2 = 0.f;
    float vals[4];
    #pragma unroll
    for (int u = 0; u < 4; u++) {
        float v = xr[tid + u * 256];
        vals[u] = v;
        s += v; s2 += v * v;
    }
    s  = warp_sum(s);
    s2 = warp_sum(s2);
    __shared__ float shs[8], shs2[8];
    int wid = tid >> 5, lane = tid & 31;
    if (lane == 0) { shs[wid] = s; shs2[wid] = s2; }
    __syncthreads();
    float ts = 0.f, ts2 = 0.f;
    #pragma unroll
    for (int i = 0; i < 8; i++) { ts += shs[i]; ts2 += shs2[i]; }
    float mean = ts * (1.0f / EE);
    float var  = ts2 * (1.0f / EE) - mean * mean;
    float rstd = rsqrtf(var + LN_EPS);
    #pragma unroll
    for (int u = 0; u < 4; u++) {
        int j = tid + u * 256;
        orow[j] = tf32r((vals[u] - mean) * rstd * gamma[j] + beta[j]);
    }
}

// ---------------------------------------------------------------------------
// cp.async helpers
// ---------------------------------------------------------------------------
__device__ __forceinline__ void cpa16(uint32_t dst, const float* src) {
    asm volatile("cp.async.cg.shared.global [%0], [%1], 16;" :: "r"(dst), "l"(src));
}
__device__ __forceinline__ void cpa_commit() {
    asm volatile("cp.async.commit_group;");
}
template<int N>
__device__ __forceinline__ void cpa_wait() {
    asm volatile("cp.async.wait_group %0;" :: "n"(N));
}

__device__ __forceinline__ void mma_tf32(float* c, const uint32_t* a, const uint32_t* b) {
    asm volatile(
        "mma.sync.aligned.m16n8k8.row.col.f32.tf32.tf32.f32 "
        "{%0,%1,%2,%3}, {%4,%5,%6,%7}, {%8,%9}, {%0,%1,%2,%3};\n"
        : "+f"(c[0]), "+f"(c[1]), "+f"(c[2]), "+f"(c[3])
        : "r"(a[0]), "r"(a[1]), "r"(a[2]), "r"(a[3]), "r"(b[0]), "r"(b[1]));
}

// ---------------------------------------------------------------------------
// Fused flash attention (causal), tf32 tensor cores. (validated in R7)
// Q/K/V live in the packed qkv buffer with row stride QKVW.
// ---------------------------------------------------------------------------
#define KST 68
#define VST 72
#define PST 132
#define KVSTAGE (128*KST + 128*VST)
#define PS_OFF  (2*KVSTAGE)
#define FA_SMEM ((PS_OFF + 128*PST) * 4)

__global__ __launch_bounds__(256, 1) void flash_kernel(
    const float* __restrict__ QKV, float* __restrict__ O)
{
    extern __shared__ float sm[];

    int mb = blockIdx.x;
    int bh = blockIdx.y;
    int b = bh >> 4, h = bh & 15;
    int m0 = mb * 128;

    const float* Qp = QKV + (long long)b * TT * QKVW + (long long)h * DD;
    const float* Kp = Qp + EE;
    const float* Vp = Qp + 2 * EE;
    float*       Op = O + (long long)b * TT * EE + (long long)h * DD;

    int tid = threadIdx.x, warp = tid >> 5, lane = tid & 31;
    int g = lane >> 2, tg = lane & 3;

    uint32_t smem_u32 = (uint32_t)__cvta_generic_to_shared(sm);

    auto load_kv = [&](int stage, int j0) {
        uint32_t base = smem_u32 + (uint32_t)(stage * KVSTAGE) * 4u;
        #pragma unroll
        for (int i = 0; i < 8; i++) {
            int idx = tid + i * 256;
            int row = idx >> 4;
            int col = (idx & 15) << 2;
            cpa16(base + (uint32_t)(row * KST + col) * 4u,
                  Kp + (long long)(j0 + row) * QKVW + col);
        }
        #pragma unroll
        for (int i = 0; i < 8; i++) {
            int idx = tid + i * 256;
            int row = idx >> 4;
            int col = (idx & 15) << 2;
            cpa16(base + (uint32_t)(128 * KST + row * VST + col) * 4u,
                  Vp + (long long)(j0 + row) * QKVW + col);
        }
    };

    // stage Q into Ps region, load KV block 0
    {
        uint32_t qbase = smem_u32 + (uint32_t)PS_OFF * 4u;
        #pragma unroll
        for (int i = 0; i < 8; i++) {
            int idx = tid + i * 256;
            int row = idx >> 4;
            int col = (idx & 15) << 2;
            cpa16(qbase + (uint32_t)(row * KST + col) * 4u,
                  Qp + (long long)(m0 + row) * QKVW + col);
        }
        cpa_commit();
        load_kv(0, 0);
        cpa_commit();
        cpa_wait<0>();
        __syncthreads();
    }

    uint32_t qf[8][4];
    {
        const float* Qs = sm + PS_OFF;
        #pragma unroll
        for (int kc = 0; kc < 8; kc++) {
            const float* qp2 = Qs + (warp * 16 + g) * KST + kc * 8 + tg;
            qf[kc][0] = __float_as_uint(0.125f * qp2[0]);
            qf[kc][1] = __float_as_uint(0.125f * qp2[8 * KST]);
            qf[kc][2] = __float_as_uint(0.125f * qp2[4]);
            qf[kc][3] = __float_as_uint(0.125f * qp2[8 * KST + 4]);
        }
    }
    __syncthreads();

    float m_[2] = {-1e30f, -1e30f};
    float l_[2] = {0.f, 0.f};
    float oacc[8][4];
    #pragma unroll
    for (int i = 0; i < 8; i++)
        #pragma unroll
        for (int c = 0; c < 4; c++) oacc[i][c] = 0.f;

    int nblk = mb;
    for (int jb = 0; jb <= nblk; jb++) {
        cpa_wait<0>();
        __syncthreads();
        if (jb < nblk) {
            load_kv((jb + 1) & 1, (jb + 1) * 128);
            cpa_commit();
        }

        const float* Ks = sm + (jb & 1) * KVSTAGE;
        const float* Vs = Ks + 128 * KST;

        float sacc[16][4];
        #pragma unroll
        for (int nf = 0; nf < 16; nf++)
            #pragma unroll
            for (int c = 0; c < 4; c++) sacc[nf][c] = 0.f;

        #pragma unroll
        for (int kc = 0; kc < 8; kc++) {
            #pragma unroll
            for (int nf = 0; nf < 16; nf++) {
                const float* bp = Ks + (nf * 8 + g) * KST + kc * 8 + tg;
                uint32_t bfr[2];
                bfr[0] = __float_as_uint(bp[0]);
                bfr[1] = __float_as_uint(bp[4]);
                mma_tf32(sacc[nf], qf[kc], bfr);
            }
        }

        if (jb == nblk) {
            int i0 = m0 + warp * 16 + g;
            #pragma unroll
            for (int nf = 0; nf < 16; nf++) {
                int j0c = jb * 128 + nf * 8 + 2 * tg;
                if (j0c     > i0)     sacc[nf][0] = -1e30f;
                if (j0c + 1 > i0)     sacc[nf][1] = -1e30f;
                if (j0c     > i0 + 8) sacc[nf][2] = -1e30f;
                if (j0c + 1 > i0 + 8) sacc[nf][3] = -1e30f;
            }
        }

        float rm0 = -1e30f, rm1 = -1e30f;
        #pragma unroll
        for (int nf = 0; nf < 16; nf++) {
            rm0 = fmaxf(rm0, fmaxf(sacc[nf][0], sacc[nf][1]));
            rm1 = fmaxf(rm1, fmaxf(sacc[nf][2], sacc[nf][3]));
        }
        rm0 = fmaxf(rm0, __shfl_xor_sync(0xffffffffu, rm0, 1));
        rm0 = fmaxf(rm0, __shfl_xor_sync(0xffffffffu, rm0, 2));
        rm1 = fmaxf(rm1, __shfl_xor_sync(0xffffffffu, rm1, 1));
        rm1 = fmaxf(rm1, __shfl_xor_sync(0xffffffffu, rm1, 2));

        float mn0 = fmaxf(m_[0], rm0), mn1 = fmaxf(m_[1], rm1);
        float sc0 = __expf(m_[0] - mn0), sc1 = __expf(m_[1] - mn1);
        m_[0] = mn0; m_[1] = mn1;

        float rs0 = 0.f, rs1 = 0.f;
        #pragma unroll
        for (int nf = 0; nf < 16; nf++) {
            sacc[nf][0] = __expf(sacc[nf][0] - mn0);
            sacc[nf][1] = __expf(sacc[nf][1] - mn0);
            sacc[nf][2] = __expf(sacc[nf][2] - mn1);
            sacc[nf][3] = __expf(sacc[nf][3] - mn1);
            rs0 += sacc[nf][0] + sacc[nf][1];
            rs1 += sacc[nf][2] + sacc[nf][3];
        }
        rs0 += __shfl_xor_sync(0xffffffffu, rs0, 1);
        rs0 += __shfl_xor_sync(0xffffffffu, rs0, 2);
        rs1 += __shfl_xor_sync(0xffffffffu, rs1, 1);
        rs1 += __shfl_xor_sync(0xffffffffu, rs1, 2);
        l_[0] = l_[0] * sc0 + rs0;
        l_[1] = l_[1] * sc1 + rs1;

        #pragma unroll
        for (int nf = 0; nf < 8; nf++) {
            oacc[nf][0] *= sc0; oacc[nf][1] *= sc0;
            oacc[nf][2] *= sc1; oacc[nf][3] *= sc1;
        }

        {
            float* Pw = sm + PS_OFF + (warp * 16 + g) * PST;
            #pragma unroll
            for (int nf = 0; nf < 16; nf++) {
                int c = nf * 8 + 2 * tg;
                float2 p0 = make_float2(tf32r(sacc[nf][0]), tf32r(sacc[nf][1]));
                float2 p1 = make_float2(tf32r(sacc[nf][2]), tf32r(sacc[nf][3]));
                *(float2*)(Pw + c)           = p0;
                *(float2*)(Pw + 8 * PST + c) = p1;
            }
        }
        __syncwarp();

        const float* Pr = sm + PS_OFF + (warp * 16 + g) * PST;
        #pragma unroll
        for (int kc = 0; kc < 16; kc++) {
            uint32_t afr[4];
            const float* ap = Pr + kc * 8 + tg;
            afr[0] = __float_as_uint(ap[0]);
            afr[1] = __float_as_uint(ap[8 * PST]);
            afr[2] = __float_as_uint(ap[4]);
            afr[3] = __float_as_uint(ap[8 * PST + 4]);
            #pragma unroll
            for (int nf = 0; nf < 8; nf++) {
                const float* bp = Vs + (kc * 8 + tg) * VST + nf * 8 + g;
                uint32_t bfr[2];
                bfr[0] = __float_as_uint(bp[0]);
                bfr[1] = __float_as_uint(bp[4 * VST]);
                mma_tf32(oacc[nf], afr, bfr);
            }
        }
    }

    float inv0 = 1.0f / l_[0], inv1 = 1.0f / l_[1];
    int r0 = m0 + warp * 16 + g;
    #pragma unroll
    for (int nf = 0; nf < 8; nf++) {
        int c = nf * 8 + 2 * tg;
        float* o0 = Op + (long long)r0 * EE + c;
        float* o1 = Op + (long long)(r0 + 8) * EE + c;
        *(float2*)o0 = make_float2(tf32r(oacc[nf][0] * inv0), tf32r(oacc[nf][1] * inv0));
        *(float2*)o1 = make_float2(tf32r(oacc[nf][2] * inv1), tf32r(oacc[nf][3] * inv1));
    }
}

// ---------------------------------------------------------------------------
// Tensor-core tf32 GEMM, BK=32, 2-stage cp.async pipeline.
// BM=128, BN in {128,64}. 256 threads = 8 warps (2 x 4), warp tile 64 x (BN/4).
// epi: 0=store 1=gelu(acc+bias) 2=C+=acc+bias 3=C+=acc ; rnd: tf32-round store
// ---------------------------------------------------------------------------
#define BM 128
#define BK 32
#define AST 36          // A smem stride (BK+4)

template<int BN, bool TB>
__global__ __launch_bounds__(256) void gemm_tc(
    const float* __restrict__ A, const float* __restrict__ Bm,
    const float* __restrict__ bias, float* __restrict__ C,
    int M, int N, int K, int lda, int ldb, int ldc,
    int epi, int rnd)
{
    constexpr int ASZ = BM * AST;
    constexpr int BSZ = TB ? BN * AST : BK * (BN + 8);
    constexpr int ST  = ASZ + BSZ;

    extern __shared__ float sm[];

    int n0 = blockIdx.x * BN;
    int m0 = blockIdx.y * BM;

    int nt = K / BK;

    int tid  = threadIdx.x;
    int warp = tid >> 5, lane = tid & 31;
    int g  = lane >> 2;
    int tg = lane & 3;
    int warp_m = warp >> 2;
    int warp_n = warp & 3;
    constexpr int NF = BN / 32;
    constexpr int WN = BN / 4;

    uint32_t smem_u32 = (uint32_t)__cvta_generic_to_shared(sm);

    auto load_tiles = [&](int st, int k0) {
        uint32_t sb = smem_u32 + (uint32_t)(st * ST) * 4u;
        // A: 128x32 = 1024 float4, 4 per thread
        #pragma unroll
        for (int i = 0; i < 4; i++) {
            int idx = tid + i * 256;
            int row = idx >> 3;
            int kc  = (idx & 7) << 2;
            cpa16(sb + (uint32_t)(row * AST + kc) * 4u,
                  A + (long long)(m0 + row) * lda + k0 + kc);
        }
        if (!TB) {
            // B: 32 x BN
            constexpr int CH = (BK * BN / 4) / 256;   // 4 (BN=128) or 2 (BN=64)
            #pragma unroll
            for (int i = 0; i < CH; i++) {
                int idx = tid + i * 256;
                int row = idx / (BN / 4);
                int nc  = (idx % (BN / 4)) << 2;
                cpa16(sb + (uint32_t)(ASZ + row * (BN + 8) + nc) * 4u,
                      Bm + (long long)(k0 + row) * ldb + n0 + nc);
            }
        } else {
            // B: BN x 32
            constexpr int CH = (BN * BK / 4) / 256;
            #pragma unroll
            for (int i = 0; i < CH; i++) {
                int idx = tid + i * 256;
                int row = idx >> 3;
                int kc  = (idx & 7) << 2;
                cpa16(sb + (uint32_t)(ASZ + row * AST + kc) * 4u,
                      Bm + (long long)(n0 + row) * ldb + k0 + kc);
            }
        }
    };

    float acc[4][NF][4];
    #pragma unroll
    for (int i = 0; i < 4; i++)
        #pragma unroll
        for (int j = 0; j < NF; j++)
            #pragma unroll
            for (int c = 0; c < 4; c++) acc[i][j][c] = 0.f;

    // prologue: stage 0
    load_tiles(0, 0);
    cpa_commit();

    for (int it = 0; it < nt; it++) {
        cpa_wait<0>();
        __syncthreads();
        if (it + 1 < nt) {
            load_tiles((it + 1) & 1, (it + 1) * BK);
            cpa_commit();
        }

        const float* Ab = sm + (it & 1) * ST;
        const float* Bb = Ab + ASZ;

        #pragma unroll
        for (int ks = 0; ks < BK; ks += 8) {
            uint32_t afr[4][4];
            #pragma unroll
            for (int mi = 0; mi < 4; mi++) {
                const float* ap = Ab + (warp_m * 64 + mi * 16 + g) * AST + ks + tg;
                afr[mi][0] = __float_as_uint(ap[0]);
                afr[mi][1] = __float_as_uint(ap[8 * AST]);
                afr[mi][2] = __float_as_uint(ap[4]);
                afr[mi][3] = __float_as_uint(ap[8 * AST + 4]);
            }
            uint32_t bfr[NF][2];
            #pragma unroll
            for (int ni = 0; ni < NF; ni++) {
                if (TB) {
                    const float* bp = Bb + (warp_n * WN + ni * 8 + g) * AST + ks + tg;
                    bfr[ni][0] = __float_as_uint(bp[0]);
                    bfr[ni][1] = __float_as_uint(bp[4]);
                } else {
                    const float* bp = Bb + (ks + tg) * (BN + 8) + warp_n * WN + ni * 8 + g;
                    bfr[ni][0] = __float_as_uint(bp[0]);
                    bfr[ni][1] = __float_as_uint(bp[4 * (BN + 8)]);
                }
            }
            #pragma unroll
            for (int mi = 0; mi < 4; mi++)
                #pragma unroll
                for (int ni = 0; ni < NF; ni++)
                    mma_tf32(acc[mi][ni], afr[mi], bfr[ni]);
        }
    }

    // epilogue (float2 per row-pair)
    #pragma unroll
    for (int mi = 0; mi < 4; mi++) {
        #pragma unroll
        for (int ni = 0; ni < NF; ni++) {
            int r0 = m0 + warp_m * 64 + mi * 16 + g;
            int c0 = n0 + warp_n * WN + ni * 8 + 2 * tg;
            #pragma unroll
            for (int p = 0; p < 2; p++) {
                int m = r0 + p * 8;
                float vx = acc[mi][ni][2 * p];
                float vy = acc[mi][ni][2 * p + 1];
                float* cp = C + (long long)m * ldc + c0;
                if (epi == 1) {
                    vx = fast_gelu(vx + bias[c0]);
                    vy = fast_gelu(vy + bias[c0 + 1]);
                } else if (epi == 2) {
                    float2 old = *(const float2*)cp;
                    vx += bias[c0]     + old.x;
                    vy += bias[c0 + 1] + old.y;
                } else if (epi == 3) {
                    float2 old = *(const float2*)cp;
                    vx += old.x;
                    vy += old.y;
                }
                if (rnd) { vx = tf32r(vx); vy = tf32r(vy); }
                *(float2*)cp = make_float2(vx, vy);
            }
        }
    }
}

// ---------------------------------------------------------------------------
// Host-side launch helper
// ---------------------------------------------------------------------------
static inline void gemm(const float* A, const float* B, const float* bias, float* C,
                        int M, int N, int K, int lda, int ldb, int ldc, bool tb,
                        int epi, int rnd)
{
    dim3 block(256);
    constexpr int ASZ = BM * AST;
    if (N % 128 == 0) {
        dim3 grid(N / 128, M / BM);
        if (tb) {
            size_t bytes = (size_t)2 * (ASZ + 128 * AST) * 4;
            gemm_tc<128, true><<<grid, block, bytes>>>(A, B, bias, C, M, N, K,
                                                       lda, ldb, ldc, epi, rnd);
        } else {
            size_t bytes = (size_t)2 * (ASZ + BK * (128 + 8)) * 4;
            gemm_tc<128, false><<<grid, block, bytes>>>(A, B, bias, C, M, N, K,
                                                        lda, ldb, ldc, epi, rnd);
        }
    } else {
        dim3 grid(N / 64, M / BM);
        if (tb) {
            size_t bytes = (size_t)2 * (ASZ + 64 * AST) * 4;
            gemm_tc<64, true><<<grid, block, bytes>>>(A, B, bias, C, M, N, K,
                                                      lda, ldb, ldc, epi, rnd);
        } else {
            size_t bytes = (size_t)2 * (ASZ + BK * (64 + 8)) * 4;
            gemm_tc<64, false><<<grid, block, bytes>>>(A, B, bias, C, M, N, K,
                                                       lda, ldb, ldc, epi, rnd);
        }
    }
}

extern "C" void kernel_launch(void* const* d_in, const int* in_sizes, int n_in,
                              void* d_out, int out_size)
{
    (void)in_sizes; (void)n_in; (void)out_size;
    const int*   idx  = (const int*)  d_in[0];
    const float* wte  = (const float*)d_in[1];
    const float* wpe  = (const float*)d_in[2];
    const float* Wq   = (const float*)d_in[3];
    const float* Wk   = (const float*)d_in[4];
    const float* Wv   = (const float*)d_in[5];
    const float* Wo   = (const float*)d_in[6];
    const float* ln1g = (const float*)d_in[7];
    const float* ln1b = (const float*)d_in[8];
    const float* ln2g = (const float*)d_in[9];
    const float* ln2b = (const float*)d_in[10];
    const float* W1   = (const float*)d_in[11];
    const float* b1   = (const float*)d_in[12];
    const float* W2   = (const float*)d_in[13];
    const float* b2   = (const float*)d_in[14];
    const float* lnfg = (const float*)d_in[15];
    const float* lnfb = (const float*)d_in[16];
    float* out = (float*)d_out;

    float *x, *h, *qkv, *o, *f;
    float *wqkv, *wo, *w1, *w2, *wt;
    cudaGetSymbolAddress((void**)&x, g_x);
    cudaGetSymbolAddress((void**)&h, g_h);
    cudaGetSymbolAddress((void**)&qkv, g_qkv);
    cudaGetSymbolAddress((void**)&o, g_o);
    cudaGetSymbolAddress((void**)&f, g_f);
    cudaGetSymbolAddress((void**)&wqkv, g_wqkv);
    cudaGetSymbolAddress((void**)&wo, g_wo);
    cudaGetSymbolAddress((void**)&w1, g_w1);
    cudaGetSymbolAddress((void**)&w2, g_w2);
    cudaGetSymbolAddress((void**)&wt, g_wte);

    cudaFuncSetAttribute(gemm_tc<128, true >, cudaFuncAttributeMaxDynamicSharedMemorySize, 96 * 1024);
    cudaFuncSetAttribute(gemm_tc<128, false>, cudaFuncAttributeMaxDynamicSharedMemorySize, 96 * 1024);
    cudaFuncSetAttribute(gemm_tc<64,  true >, cudaFuncAttributeMaxDynamicSharedMemorySize, 96 * 1024);
    cudaFuncSetAttribute(gemm_tc<64,  false>, cudaFuncAttributeMaxDynamicSharedMemorySize, 96 * 1024);
    cudaFuncSetAttribute(flash_kernel, cudaFuncAttributeMaxDynamicSharedMemorySize, FA_SMEM);

    // pack + pre-round weights to tf32
    {
        long long nqkv = (long long)LL * EE * QKVW / 4;
        pack_qkv<<<(unsigned)((nqkv + 255) / 256), 256>>>(Wq, Wk, Wv, wqkv);
        long long nqk = (long long)LL * EE * EE / 4;
        round_copy<<<(unsigned)((nqk + 255) / 256), 256>>>(Wo, wo, nqk);
        long long nff = (long long)LL * EE * FF / 4;
        round_copy<<<(unsigned)((nff + 255) / 256), 256>>>(W1, w1, nff);
        round_copy<<<(unsigned)((nff + 255) / 256), 256>>>(W2, w2, nff);
        long long nte = (long long)VV * EE / 4;
        round_copy<<<(unsigned)((nte + 255) / 256), 256>>>(wte, wt, nte);
    }

    embed_kernel<<<(MM * EE) / 256, 256>>>(idx, wte, wpe, x);

    for (int l = 0; l < LL; l++) {
        ln_kernel<<<MM, 256>>>(x, ln1g + (long long)l * EE, ln1b + (long long)l * EE, h);

        // fused QKV projection: [4096 x 3072] = h @ WqkvPacked
        gemm(h, wqkv + (long long)l * EE * QKVW, nullptr, qkv,
             MM, QKVW, EE, EE, QKVW, QKVW, false, 0, 1);

        // fused causal attention
        {
            dim3 grid(TT / 128, BB * HH);
            flash_kernel<<<grid, 256, FA_SMEM>>>(qkv, o);
        }

        gemm(o, wo + (long long)l * EE * EE, nullptr, x,
             MM, EE, EE, EE, EE, EE, false, 3, 0);

        ln_kernel<<<MM, 256>>>(x, ln2g + (long long)l * EE, ln2b + (long long)l * EE, h);

        gemm(h, w1 + (long long)l * EE * FF, b1 + (long long)l * FF, f,
             MM, FF, EE, EE, FF, FF, false, 1, 1);

        gemm(f, w2 + (long long)l * FF * EE, b2 + (long long)l * EE, x,
             MM, EE, FF, FF, EE, EE, false, 2, 0);
    }

    ln_kernel<<<MM, 256>>>(x, lnfg, lnfb, h);

    gemm(h, wt, nullptr, out, MM, VV, EE, EE, EE, VV, true, 0, 0);
}

// round 9
// speedup vs baseline: 4.3234x; 1.0082x over previous
#include <cuda_runtime.h>
#include <cuda_bf16.h>
#include <math.h>
#include <stdint.h>

// Problem constants
#define BB 4
#define TT 1024
#define EE 1024
#define HH 16
#define DD 64
#define FF 4096
#define LL 6
#define VV 32000
#define MM (BB*TT)
#define QKVW 3072
#define LN_EPS 1e-5f

// ---------------------------------------------------------------------------
// Scratch (device globals; no cudaMalloc allowed)
// ---------------------------------------------------------------------------
__device__ float g_x[(size_t)MM * EE];
__device__ float g_h[(size_t)MM * EE];
__device__ float g_qkv[(size_t)MM * QKVW];
__device__ float g_o[(size_t)MM * EE];
__device__ float g_f[(size_t)MM * FF];
// pre-rounded (tf32-in-fp32) weights
__device__ float g_wqkv[(size_t)LL * EE * QKVW];
__device__ float g_wo[(size_t)LL * EE * EE];
__device__ float g_w1[(size_t)LL * EE * FF];
__device__ float g_w2[(size_t)LL * FF * EE];
__device__ float g_wte[(size_t)VV * EE];

__device__ __forceinline__ float tf32r(float x) {
    uint32_t u;
    asm("cvt.rna.tf32.f32 %0, %1;" : "=r"(u) : "f"(x));
    return __uint_as_float(u);
}

// Fast exact-grade GELU: A&S 7.1.26 erf, |abs err| <= 1.5e-7
__device__ __forceinline__ float fast_gelu(float v) {
    float x  = v * 0.70710678118654752f;
    float ax = fabsf(x);
    float t  = 1.0f / (1.0f + 0.3275911f * ax);
    float p  = ((((1.061405429f * t - 1.453152027f) * t + 1.421413741f) * t
                 - 0.284496736f) * t + 0.254829592f) * t;
    float er = 1.0f - p * __expf(-x * x);
    er = copysignf(er, x);
    return 0.5f * v * (1.0f + er);
}

// ---------------------------------------------------------------------------
// Round-copy: out[i] = tf32(in[i])
// ---------------------------------------------------------------------------
__global__ __launch_bounds__(256) void round_copy(const float* __restrict__ in,
                                                  float* __restrict__ out, long long n4)
{
    long long i = (long long)blockIdx.x * 256 + threadIdx.x;
    if (i < n4) {
        float4 v = ((const float4*)in)[i];
        v.x = tf32r(v.x); v.y = tf32r(v.y); v.z = tf32r(v.z); v.w = tf32r(v.w);
        ((float4*)out)[i] = v;
    }
}

// Pack Wq|Wk|Wv into [L][E][3E], tf32-rounded.
__global__ __launch_bounds__(256) void pack_qkv(const float* __restrict__ Wq,
                                                const float* __restrict__ Wk,
                                                const float* __restrict__ Wv,
                                                float* __restrict__ out)
{
    long long i = (long long)blockIdx.x * 256 + threadIdx.x;   // float4 index
    const long long row_f4 = QKVW / 4;                          // 768
    long long row  = i / row_f4;                                // l*EE + kk
    int col4 = (int)(i - row * row_f4);
    int sel  = col4 / (EE / 4);
    int c    = col4 - sel * (EE / 4);
    const float* src = (sel == 0 ? Wq : sel == 1 ? Wk : Wv);
    float4 v = ((const float4*)(src + row * EE))[c];
    v.x = tf32r(v.x); v.y = tf32r(v.y); v.z = tf32r(v.z); v.w = tf32r(v.w);
    ((float4*)out)[i] = v;
}

// ---------------------------------------------------------------------------
// Embedding
// ---------------------------------------------------------------------------
__global__ void embed_kernel(const int* __restrict__ idx,
                             const float* __restrict__ wte,
                             const float* __restrict__ wpe,
                             float* __restrict__ x)
{
    long long i = (long long)blockIdx.x * blockDim.x + threadIdx.x;
    int bt = (int)(i >> 10);
    int e  = (int)(i & 1023);
    int t  = bt & (TT - 1);
    x[i] = wte[(long long)idx[bt] * EE + e] + wpe[(long long)t * EE + e];
}

// ---------------------------------------------------------------------------
// LayerNorm (output tf32-rounded; only feeds GEMMs)
// ---------------------------------------------------------------------------
__device__ __forceinline__ float warp_sum(float v) {
    #pragma unroll
    for (int o = 16; o > 0; o >>= 1) v += __shfl_xor_sync(0xffffffffu, v, o);
    return v;
}

__global__ __launch_bounds__(256) void ln_kernel(const float* __restrict__ x,
                                                 const float* __restrict__ gamma,
                                                 const float* __restrict__ beta,
                                                 float* __restrict__ out)
{
    int row = blockIdx.x;
    const float* xr = x + (long long)row * EE;
    float* orow = out + (long long)row * EE;
    int tid = threadIdx.x;

    float s = 0.f, s2 = 0.f;
    float vals[4];
    #pragma unroll
    for (int u = 0; u < 4; u++) {
        float v = xr[tid + u * 256];
        vals[u] = v;
        s += v; s2 += v * v;
    }
    s  = warp_sum(s);
    s2 = warp_sum(s2);
    __shared__ float shs[8], shs2[8];
    int wid = tid >> 5, lane = tid & 31;
    if (lane == 0) { shs[wid] = s; shs2[wid] = s2; }
    __syncthreads();
    float ts = 0.f, ts2 = 0.f;
    #pragma unroll
    for (int i = 0; i < 8; i++) { ts += shs[i]; ts2 += shs2[i]; }
    float mean = ts * (1.0f / EE);
    float var  = ts2 * (1.0f / EE) - mean * mean;
    float rstd = rsqrtf(var + LN_EPS);
    #pragma unroll
    for (int u = 0; u < 4; u++) {
        int j = tid + u * 256;
        orow[j] = tf32r((vals[u] - mean) * rstd * gamma[j] + beta[j]);
    }
}

// ---------------------------------------------------------------------------
// cp.async helpers
// ---------------------------------------------------------------------------
__device__ __forceinline__ void cpa16(uint32_t dst, const float* src) {
    asm volatile("cp.async.cg.shared.global [%0], [%1], 16;" :: "r"(dst), "l"(src));
}
__device__ __forceinline__ void cpa_commit() {
    asm volatile("cp.async.commit_group;");
}
template<int N>
__device__ __forceinline__ void cpa_wait() {
    asm volatile("cp.async.wait_group %0;" :: "n"(N));
}

__device__ __forceinline__ void mma_tf32(float* c, const uint32_t* a, const uint32_t* b) {
    asm volatile(
        "mma.sync.aligned.m16n8k8.row.col.f32.tf32.tf32.f32 "
        "{%0,%1,%2,%3}, {%4,%5,%6,%7}, {%8,%9}, {%0,%1,%2,%3};\n"
        : "+f"(c[0]), "+f"(c[1]), "+f"(c[2]), "+f"(c[3])
        : "r"(a[0]), "r"(a[1]), "r"(a[2]), "r"(a[3]), "r"(b[0]), "r"(b[1]));
}

// ---------------------------------------------------------------------------
// Fused flash attention (causal), tf32 tensor cores. (validated in R7/R8)
// Heavy diagonal blocks scheduled first (mb reversed) for better packing.
// ---------------------------------------------------------------------------
#define KST 68
#define VST 72
#define PST 132
#define KVSTAGE (128*KST + 128*VST)
#define PS_OFF  (2*KVSTAGE)
#define FA_SMEM ((PS_OFF + 128*PST) * 4)

__global__ __launch_bounds__(256, 1) void flash_kernel(
    const float* __restrict__ QKV, float* __restrict__ O)
{
    extern __shared__ float sm[];

    int mb = gridDim.x - 1 - blockIdx.x;   // heavy blocks first
    int bh = blockIdx.y;
    int b = bh >> 4, h = bh & 15;
    int m0 = mb * 128;

    const float* Qp = QKV + (long long)b * TT * QKVW + (long long)h * DD;
    const float* Kp = Qp + EE;
    const float* Vp = Qp + 2 * EE;
    float*       Op = O + (long long)b * TT * EE + (long long)h * DD;

    int tid = threadIdx.x, warp = tid >> 5, lane = tid & 31;
    int g = lane >> 2, tg = lane & 3;

    uint32_t smem_u32 = (uint32_t)__cvta_generic_to_shared(sm);

    auto load_kv = [&](int stage, int j0) {
        uint32_t base = smem_u32 + (uint32_t)(stage * KVSTAGE) * 4u;
        #pragma unroll
        for (int i = 0; i < 8; i++) {
            int idx = tid + i * 256;
            int row = idx >> 4;
            int col = (idx & 15) << 2;
            cpa16(base + (uint32_t)(row * KST + col) * 4u,
                  Kp + (long long)(j0 + row) * QKVW + col);
        }
        #pragma unroll
        for (int i = 0; i < 8; i++) {
            int idx = tid + i * 256;
            int row = idx >> 4;
            int col = (idx & 15) << 2;
            cpa16(base + (uint32_t)(128 * KST + row * VST + col) * 4u,
                  Vp + (long long)(j0 + row) * QKVW + col);
        }
    };

    // stage Q into Ps region, load KV block 0
    {
        uint32_t qbase = smem_u32 + (uint32_t)PS_OFF * 4u;
        #pragma unroll
        for (int i = 0; i < 8; i++) {
            int idx = tid + i * 256;
            int row = idx >> 4;
            int col = (idx & 15) << 2;
            cpa16(qbase + (uint32_t)(row * KST + col) * 4u,
                  Qp + (long long)(m0 + row) * QKVW + col);
        }
        cpa_commit();
        load_kv(0, 0);
        cpa_commit();
        cpa_wait<0>();
        __syncthreads();
    }

    uint32_t qf[8][4];
    {
        const float* Qs = sm + PS_OFF;
        #pragma unroll
        for (int kc = 0; kc < 8; kc++) {
            const float* qp2 = Qs + (warp * 16 + g) * KST + kc * 8 + tg;
            qf[kc][0] = __float_as_uint(0.125f * qp2[0]);
            qf[kc][1] = __float_as_uint(0.125f * qp2[8 * KST]);
            qf[kc][2] = __float_as_uint(0.125f * qp2[4]);
            qf[kc][3] = __float_as_uint(0.125f * qp2[8 * KST + 4]);
        }
    }
    __syncthreads();

    float m_[2] = {-1e30f, -1e30f};
    float l_[2] = {0.f, 0.f};
    float oacc[8][4];
    #pragma unroll
    for (int i = 0; i < 8; i++)
        #pragma unroll
        for (int c = 0; c < 4; c++) oacc[i][c] = 0.f;

    int nblk = mb;
    for (int jb = 0; jb <= nblk; jb++) {
        cpa_wait<0>();
        __syncthreads();
        if (jb < nblk) {
            load_kv((jb + 1) & 1, (jb + 1) * 128);
            cpa_commit();
        }

        const float* Ks = sm + (jb & 1) * KVSTAGE;
        const float* Vs = Ks + 128 * KST;

        float sacc[16][4];
        #pragma unroll
        for (int nf = 0; nf < 16; nf++)
            #pragma unroll
            for (int c = 0; c < 4; c++) sacc[nf][c] = 0.f;

        #pragma unroll
        for (int kc = 0; kc < 8; kc++) {
            #pragma unroll
            for (int nf = 0; nf < 16; nf++) {
                const float* bp = Ks + (nf * 8 + g) * KST + kc * 8 + tg;
                uint32_t bfr[2];
                bfr[0] = __float_as_uint(bp[0]);
                bfr[1] = __float_as_uint(bp[4]);
                mma_tf32(sacc[nf], qf[kc], bfr);
            }
        }

        if (jb == nblk) {
            int i0 = m0 + warp * 16 + g;
            #pragma unroll
            for (int nf = 0; nf < 16; nf++) {
                int j0c = jb * 128 + nf * 8 + 2 * tg;
                if (j0c     > i0)     sacc[nf][0] = -1e30f;
                if (j0c + 1 > i0)     sacc[nf][1] = -1e30f;
                if (j0c     > i0 + 8) sacc[nf][2] = -1e30f;
                if (j0c + 1 > i0 + 8) sacc[nf][3] = -1e30f;
            }
        }

        float rm0 = -1e30f, rm1 = -1e30f;
        #pragma unroll
        for (int nf = 0; nf < 16; nf++) {
            rm0 = fmaxf(rm0, fmaxf(sacc[nf][0], sacc[nf][1]));
            rm1 = fmaxf(rm1, fmaxf(sacc[nf][2], sacc[nf][3]));
        }
        rm0 = fmaxf(rm0, __shfl_xor_sync(0xffffffffu, rm0, 1));
        rm0 = fmaxf(rm0, __shfl_xor_sync(0xffffffffu, rm0, 2));
        rm1 = fmaxf(rm1, __shfl_xor_sync(0xffffffffu, rm1, 1));
        rm1 = fmaxf(rm1, __shfl_xor_sync(0xffffffffu, rm1, 2));

        float mn0 = fmaxf(m_[0], rm0), mn1 = fmaxf(m_[1], rm1);
        float sc0 = __expf(m_[0] - mn0), sc1 = __expf(m_[1] - mn1);
        m_[0] = mn0; m_[1] = mn1;

        float rs0 = 0.f, rs1 = 0.f;
        #pragma unroll
        for (int nf = 0; nf < 16; nf++) {
            sacc[nf][0] = __expf(sacc[nf][0] - mn0);
            sacc[nf][1] = __expf(sacc[nf][1] - mn0);
            sacc[nf][2] = __expf(sacc[nf][2] - mn1);
            sacc[nf][3] = __expf(sacc[nf][3] - mn1);
            rs0 += sacc[nf][0] + sacc[nf][1];
            rs1 += sacc[nf][2] + sacc[nf][3];
        }
        rs0 += __shfl_xor_sync(0xffffffffu, rs0, 1);
        rs0 += __shfl_xor_sync(0xffffffffu, rs0, 2);
        rs1 += __shfl_xor_sync(0xffffffffu, rs1, 1);
        rs1 += __shfl_xor_sync(0xffffffffu, rs1, 2);
        l_[0] = l_[0] * sc0 + rs0;
        l_[1] = l_[1] * sc1 + rs1;

        #pragma unroll
        for (int nf = 0; nf < 8; nf++) {
            oacc[nf][0] *= sc0; oacc[nf][1] *= sc0;
            oacc[nf][2] *= sc1; oacc[nf][3] *= sc1;
        }

        {
            float* Pw = sm + PS_OFF + (warp * 16 + g) * PST;
            #pragma unroll
            for (int nf = 0; nf < 16; nf++) {
                int c = nf * 8 + 2 * tg;
                float2 p0 = make_float2(tf32r(sacc[nf][0]), tf32r(sacc[nf][1]));
                float2 p1 = make_float2(tf32r(sacc[nf][2]), tf32r(sacc[nf][3]));
                *(float2*)(Pw + c)           = p0;
                *(float2*)(Pw + 8 * PST + c) = p1;
            }
        }
        __syncwarp();

        const float* Pr = sm + PS_OFF + (warp * 16 + g) * PST;
        #pragma unroll
        for (int kc = 0; kc < 16; kc++) {
            uint32_t afr[4];
            const float* ap = Pr + kc * 8 + tg;
            afr[0] = __float_as_uint(ap[0]);
            afr[1] = __float_as_uint(ap[8 * PST]);
            afr[2] = __float_as_uint(ap[4]);
            afr[3] = __float_as_uint(ap[8 * PST + 4]);
            #pragma unroll
            for (int nf = 0; nf < 8; nf++) {
                const float* bp = Vs + (kc * 8 + tg) * VST + nf * 8 + g;
                uint32_t bfr[2];
                bfr[0] = __float_as_uint(bp[0]);
                bfr[1] = __float_as_uint(bp[4 * VST]);
                mma_tf32(oacc[nf], afr, bfr);
            }
        }
    }

    float inv0 = 1.0f / l_[0], inv1 = 1.0f / l_[1];
    int r0 = m0 + warp * 16 + g;
    #pragma unroll
    for (int nf = 0; nf < 8; nf++) {
        int c = nf * 8 + 2 * tg;
        float* o0 = Op + (long long)r0 * EE + c;
        float* o1 = Op + (long long)(r0 + 8) * EE + c;
        *(float2*)o0 = make_float2(tf32r(oacc[nf][0] * inv0), tf32r(oacc[nf][1] * inv0));
        *(float2*)o1 = make_float2(tf32r(oacc[nf][2] * inv1), tf32r(oacc[nf][3] * inv1));
    }
}

// ---------------------------------------------------------------------------
// Tensor-core tf32 GEMM, BK=32, 3-stage cp.async pipeline (wait<1>).
// Grid: x = M-tiles (fast), y = N-tiles -> consecutive CTAs share B tiles and
// keep A (<=16MB) L2-resident; critical for lm_head where B = 131MB.
// epi: 0=store 1=gelu(acc+bias) 2=C+=acc+bias 3=C+=acc ; rnd: tf32-round store
// ---------------------------------------------------------------------------
#define BM 128
#define BK 32
#define AST 36          // A smem stride (BK+4)
#define NSTG 3

template<int BN, bool TB>
__global__ __launch_bounds__(256, 2) void gemm_tc(
    const float* __restrict__ A, const float* __restrict__ Bm,
    const float* __restrict__ bias, float* __restrict__ C,
    int M, int N, int K, int lda, int ldb, int ldc,
    int epi, int rnd)
{
    constexpr int ASZ = BM * AST;
    constexpr int BSZ = TB ? BN * AST : BK * (BN + 8);
    constexpr int ST  = ASZ + BSZ;

    extern __shared__ float sm[];

    int m0 = blockIdx.x * BM;
    int n0 = blockIdx.y * BN;

    int nt = K / BK;

    int tid  = threadIdx.x;
    int warp = tid >> 5, lane = tid & 31;
    int g  = lane >> 2;
    int tg = lane & 3;
    int warp_m = warp >> 2;
    int warp_n = warp & 3;
    constexpr int NF = BN / 32;
    constexpr int WN = BN / 4;

    uint32_t smem_u32 = (uint32_t)__cvta_generic_to_shared(sm);

    auto load_tiles = [&](int st, int k0) {
        uint32_t sb = smem_u32 + (uint32_t)(st * ST) * 4u;
        // A: 128x32 = 1024 float4, 4 per thread
        #pragma unroll
        for (int i = 0; i < 4; i++) {
            int idx = tid + i * 256;
            int row = idx >> 3;
            int kc  = (idx & 7) << 2;
            cpa16(sb + (uint32_t)(row * AST + kc) * 4u,
                  A + (long long)(m0 + row) * lda + k0 + kc);
        }
        if (!TB) {
            constexpr int CH = (BK * BN / 4) / 256;
            #pragma unroll
            for (int i = 0; i < CH; i++) {
                int idx = tid + i * 256;
                int row = idx / (BN / 4);
                int nc  = (idx % (BN / 4)) << 2;
                cpa16(sb + (uint32_t)(ASZ + row * (BN + 8) + nc) * 4u,
                      Bm + (long long)(k0 + row) * ldb + n0 + nc);
            }
        } else {
            constexpr int CH = (BN * BK / 4) / 256;
            #pragma unroll
            for (int i = 0; i < CH; i++) {
                int idx = tid + i * 256;
                int row = idx >> 3;
                int kc  = (idx & 7) << 2;
                cpa16(sb + (uint32_t)(ASZ + row * AST + kc) * 4u,
                      Bm + (long long)(n0 + row) * ldb + k0 + kc);
            }
        }
    };

    float acc[4][NF][4];
    #pragma unroll
    for (int i = 0; i < 4; i++)
        #pragma unroll
        for (int j = 0; j < NF; j++)
            #pragma unroll
            for (int c = 0; c < 4; c++) acc[i][j][c] = 0.f;

    // prologue: stages 0,1 (one group each — group count stays uniform)
    load_tiles(0, 0);
    cpa_commit();
    if (nt > 1) load_tiles(1, BK);
    cpa_commit();

    int cs = 0;          // compute stage
    int ps = 2;          // stage written by this iteration's prefetch
    for (int it = 0; it < nt; it++) {
        cpa_wait<1>();           // all groups except newest done -> stage cs ready
        __syncthreads();         // nobody still reads stage ps (computed at it-1)
        if (it + 2 < nt) load_tiles(ps, (it + 2) * BK);
        cpa_commit();            // empty group when no load keeps counts aligned

        const float* Ab = sm + cs * ST;
        const float* Bb = Ab + ASZ;

        #pragma unroll
        for (int ks = 0; ks < BK; ks += 8) {
            uint32_t afr[4][4];
            #pragma unroll
            for (int mi = 0; mi < 4; mi++) {
                const float* ap = Ab + (warp_m * 64 + mi * 16 + g) * AST + ks + tg;
                afr[mi][0] = __float_as_uint(ap[0]);
                afr[mi][1] = __float_as_uint(ap[8 * AST]);
                afr[mi][2] = __float_as_uint(ap[4]);
                afr[mi][3] = __float_as_uint(ap[8 * AST + 4]);
            }
            uint32_t bfr[NF][2];
            #pragma unroll
            for (int ni = 0; ni < NF; ni++) {
                if (TB) {
                    const float* bp = Bb + (warp_n * WN + ni * 8 + g) * AST + ks + tg;
                    bfr[ni][0] = __float_as_uint(bp[0]);
                    bfr[ni][1] = __float_as_uint(bp[4]);
                } else {
                    const float* bp = Bb + (ks + tg) * (BN + 8) + warp_n * WN + ni * 8 + g;
                    bfr[ni][0] = __float_as_uint(bp[0]);
                    bfr[ni][1] = __float_as_uint(bp[4 * (BN + 8)]);
                }
            }
            #pragma unroll
            for (int mi = 0; mi < 4; mi++)
                #pragma unroll
                for (int ni = 0; ni < NF; ni++)
                    mma_tf32(acc[mi][ni], afr[mi], bfr[ni]);
        }

        cs++; if (cs == NSTG) cs = 0;
        ps++; if (ps == NSTG) ps = 0;
    }

    // epilogue (float2 per row-pair)
    #pragma unroll
    for (int mi = 0; mi < 4; mi++) {
        #pragma unroll
        for (int ni = 0; ni < NF; ni++) {
            int r0 = m0 + warp_m * 64 + mi * 16 + g;
            int c0 = n0 + warp_n * WN + ni * 8 + 2 * tg;
            #pragma unroll
            for (int p = 0; p < 2; p++) {
                int m = r0 + p * 8;
                float vx = acc[mi][ni][2 * p];
                float vy = acc[mi][ni][2 * p + 1];
                float* cp = C + (long long)m * ldc + c0;
                if (epi == 1) {
                    vx = fast_gelu(vx + bias[c0]);
                    vy = fast_gelu(vy + bias[c0 + 1]);
                } else if (epi == 2) {
                    float2 old = *(const float2*)cp;
                    vx += bias[c0]     + old.x;
                    vy += bias[c0 + 1] + old.y;
                } else if (epi == 3) {
                    float2 old = *(const float2*)cp;
                    vx += old.x;
                    vy += old.y;
                }
                if (rnd) { vx = tf32r(vx); vy = tf32r(vy); }
                *(float2*)cp = make_float2(vx, vy);
            }
        }
    }
}

// ---------------------------------------------------------------------------
// Host-side launch helper (grid: x = M-tiles, y = N-tiles)
// ---------------------------------------------------------------------------
static inline void gemm(const float* A, const float* B, const float* bias, float* C,
                        int M, int N, int K, int lda, int ldb, int ldc, bool tb,
                        int epi, int rnd)
{
    dim3 block(256);
    constexpr int ASZ = BM * AST;
    if (N % 128 == 0) {
        dim3 grid(M / BM, N / 128);
        if (tb) {
            size_t bytes = (size_t)NSTG * (ASZ + 128 * AST) * 4;
            gemm_tc<128, true><<<grid, block, bytes>>>(A, B, bias, C, M, N, K,
                                                       lda, ldb, ldc, epi, rnd);
        } else {
            size_t bytes = (size_t)NSTG * (ASZ + BK * (128 + 8)) * 4;
            gemm_tc<128, false><<<grid, block, bytes>>>(A, B, bias, C, M, N, K,
                                                        lda, ldb, ldc, epi, rnd);
        }
    } else {
        dim3 grid(M / BM, N / 64);
        if (tb) {
            size_t bytes = (size_t)NSTG * (ASZ + 64 * AST) * 4;
            gemm_tc<64, true><<<grid, block, bytes>>>(A, B, bias, C, M, N, K,
                                                      lda, ldb, ldc, epi, rnd);
        } else {
            size_t bytes = (size_t)NSTG * (ASZ + BK * (64 + 8)) * 4;
            gemm_tc<64, false><<<grid, block, bytes>>>(A, B, bias, C, M, N, K,
                                                       lda, ldb, ldc, epi, rnd);
        }
    }
}

extern "C" void kernel_launch(void* const* d_in, const int* in_sizes, int n_in,
                              void* d_out, int out_size)
{
    (void)in_sizes; (void)n_in; (void)out_size;
    const int*   idx  = (const int*)  d_in[0];
    const float* wte  = (const float*)d_in[1];
    const float* wpe  = (const float*)d_in[2];
    const float* Wq   = (const float*)d_in[3];
    const float* Wk   = (const float*)d_in[4];
    const float* Wv   = (const float*)d_in[5];
    const float* Wo   = (const float*)d_in[6];
    const float* ln1g = (const float*)d_in[7];
    const float* ln1b = (const float*)d_in[8];
    const float* ln2g = (const float*)d_in[9];
    const float* ln2b = (const float*)d_in[10];
    const float* W1   = (const float*)d_in[11];
    const float* b1   = (const float*)d_in[12];
    const float* W2   = (const float*)d_in[13];
    const float* b2   = (const float*)d_in[14];
    const float* lnfg = (const float*)d_in[15];
    const float* lnfb = (const float*)d_in[16];
    float* out = (float*)d_out;

    float *x, *h, *qkv, *o, *f;
    float *wqkv, *wo, *w1, *w2, *wt;
    cudaGetSymbolAddress((void**)&x, g_x);
    cudaGetSymbolAddress((void**)&h, g_h);
    cudaGetSymbolAddress((void**)&qkv, g_qkv);
    cudaGetSymbolAddress((void**)&o, g_o);
    cudaGetSymbolAddress((void**)&f, g_f);
    cudaGetSymbolAddress((void**)&wqkv, g_wqkv);
    cudaGetSymbolAddress((void**)&wo, g_wo);
    cudaGetSymbolAddress((void**)&w1, g_w1);
    cudaGetSymbolAddress((void**)&w2, g_w2);
    cudaGetSymbolAddress((void**)&wt, g_wte);

    cudaFuncSetAttribute(gemm_tc<128, true >, cudaFuncAttributeMaxDynamicSharedMemorySize, 128 * 1024);
    cudaFuncSetAttribute(gemm_tc<128, false>, cudaFuncAttributeMaxDynamicSharedMemorySize, 128 * 1024);
    cudaFuncSetAttribute(gemm_tc<64,  true >, cudaFuncAttributeMaxDynamicSharedMemorySize, 128 * 1024);
    cudaFuncSetAttribute(gemm_tc<64,  false>, cudaFuncAttributeMaxDynamicSharedMemorySize, 128 * 1024);
    cudaFuncSetAttribute(flash_kernel, cudaFuncAttributeMaxDynamicSharedMemorySize, FA_SMEM);

    // pack + pre-round weights to tf32
    {
        long long nqkv = (long long)LL * EE * QKVW / 4;
        pack_qkv<<<(unsigned)((nqkv + 255) / 256), 256>>>(Wq, Wk, Wv, wqkv);
        long long nqk = (long long)LL * EE * EE / 4;
        round_copy<<<(unsigned)((nqk + 255) / 256), 256>>>(Wo, wo, nqk);
        long long nff = (long long)LL * EE * FF / 4;
        round_copy<<<(unsigned)((nff + 255) / 256), 256>>>(W1, w1, nff);
        round_copy<<<(unsigned)((nff + 255) / 256), 256>>>(W2, w2, nff);
        long long nte = (long long)VV * EE / 4;
        round_copy<<<(unsigned)((nte + 255) / 256), 256>>>(wte, wt, nte);
    }

    embed_kernel<<<(MM * EE) / 256, 256>>>(idx, wte, wpe, x);

    for (int l = 0; l < LL; l++) {
        ln_kernel<<<MM, 256>>>(x, ln1g + (long long)l * EE, ln1b + (long long)l * EE, h);

        // fused QKV projection: [4096 x 3072] = h @ WqkvPacked
        gemm(h, wqkv + (long long)l * EE * QKVW, nullptr, qkv,
             MM, QKVW, EE, EE, QKVW, QKVW, false, 0, 1);

        // fused causal attention
        {
            dim3 grid(TT / 128, BB * HH);
            flash_kernel<<<grid, 256, FA_SMEM>>>(qkv, o);
        }

        gemm(o, wo + (long long)l * EE * EE, nullptr, x,
             MM, EE, EE, EE, EE, EE, false, 3, 0);

        ln_kernel<<<MM, 256>>>(x, ln2g + (long long)l * EE, ln2b + (long long)l * EE, h);

        gemm(h, w1 + (long long)l * EE * FF, b1 + (long long)l * FF, f,
             MM, FF, EE, EE, FF, FF, false, 1, 1);

        gemm(f, w2 + (long long)l * FF * EE, b2 + (long long)l * EE, x,
             MM, EE, FF, FF, EE, EE, false, 2, 0);
    }

    ln_kernel<<<MM, 256>>>(x, lnfg, lnfb, h);

    gemm(h, wt, nullptr, out, MM, VV, EE, EE, EE, VV, true, 0, 0);
}